// round 10
// baseline (speedup 1.0000x reference)
#include <cuda_runtime.h>
#include <cuda_bf16.h>
#include <cstdint>

// ---------------- problem constants ----------------
#define LE 2048
#define LA 2048
#define CM 256          // d_model
#define HN 8            // heads
#define DH 32           // head dim
#define DF 1024         // ffn dim
#define LQ 3072         // 2048 + 1024 remain
#define LK 4096         // 2048 + 2048
#define SCALE 0.17677669529663687f   // 1/sqrt(32)

#define HT_SIZE 4096
#define HT_MASK (HT_SIZE - 1)
#define HT_EMPTY 0xFFFFFFFFFFFFFFFFull

// ---------------- fp32 scratch ----------------
__device__ float d_fused[LE * CM];
__device__ float d_q[LQ * CM];
__device__ float d_res1[LQ * CM];
__device__ float d_yq[LQ * CM];
__device__ float d_res2[LQ * CM];
__device__ int d_matched[LE];
__device__ int d_afe[LE];
__device__ int d_unmatched[LA];
__device__ int d_remain[LA];
__device__ unsigned long long d_ht[HT_SIZE];

// ---------------- bf16 scratch ----------------
__device__ __nv_bfloat16 b_fi_h[LE * 2 * CM], b_fi_l[LE * 2 * CM];
__device__ __nv_bfloat16 b_h1_h[LE * CM], b_h1_l[LE * CM];
__device__ __nv_bfloat16 b_h2_h[LE * CM], b_h2_l[LE * CM];
__device__ __nv_bfloat16 b_q_h[LQ * CM], b_q_l[LQ * CM];
__device__ __nv_bfloat16 b_kv_h[LK * CM], b_kv_l[LK * CM];
__device__ __nv_bfloat16 b_Q[LQ * CM];
__device__ __nv_bfloat16 b_K[LK * CM];
__device__ __nv_bfloat16 b_V[LK * CM];
__device__ __nv_bfloat16 b_at_h[LQ * CM], b_at_l[LQ * CM];
__device__ __nv_bfloat16 b_yq_h[LQ * CM], b_yq_l[LQ * CM];
__device__ __nv_bfloat16 b_ff_h[LQ * DF], b_ff_l[LQ * DF];
__device__ __nv_bfloat16 b_wf1_h[CM * 2 * CM], b_wf1_l[CM * 2 * CM];
__device__ __nv_bfloat16 b_wf2_h[CM * CM], b_wf2_l[CM * CM];
__device__ __nv_bfloat16 b_wf3_h[CM * CM], b_wf3_l[CM * CM];
__device__ __nv_bfloat16 b_wqkv_h[3 * CM * CM], b_wqkv_l[3 * CM * CM];
__device__ __nv_bfloat16 b_wo_h[CM * CM], b_wo_l[CM * CM];
__device__ __nv_bfloat16 b_w1_h[DF * CM], b_w1_l[DF * CM];
__device__ __nv_bfloat16 b_w2_h[CM * DF], b_w2_l[CM * DF];

// ---------------- helpers ----------------
static __device__ __forceinline__ uint32_t smem_u32(const void* p) {
    return (uint32_t)__cvta_generic_to_shared(p);
}
static __device__ __forceinline__ void ldm4(uint32_t* r, const void* p) {
    uint32_t a = smem_u32(p);
    asm volatile("ldmatrix.sync.aligned.m8n8.x4.shared.b16 {%0,%1,%2,%3}, [%4];\n"
                 : "=r"(r[0]), "=r"(r[1]), "=r"(r[2]), "=r"(r[3]) : "r"(a));
}
static __device__ __forceinline__ void ldm4t(uint32_t* r, const void* p) {
    uint32_t a = smem_u32(p);
    asm volatile("ldmatrix.sync.aligned.m8n8.x4.trans.shared.b16 {%0,%1,%2,%3}, [%4];\n"
                 : "=r"(r[0]), "=r"(r[1]), "=r"(r[2]), "=r"(r[3]) : "r"(a));
}
static __device__ __forceinline__ void mma_bf16(float* c, const uint32_t* a, const uint32_t* b) {
    asm volatile("mma.sync.aligned.m16n8k16.row.col.f32.bf16.bf16.f32 "
                 "{%0,%1,%2,%3}, {%4,%5,%6,%7}, {%8,%9}, {%0,%1,%2,%3};\n"
                 : "+f"(c[0]), "+f"(c[1]), "+f"(c[2]), "+f"(c[3])
                 : "r"(a[0]), "r"(a[1]), "r"(a[2]), "r"(a[3]), "r"(b[0]), "r"(b[1]));
}
static __device__ __forceinline__ uint32_t packbf(float lo, float hi) {
    uint32_t r;
    asm("cvt.rn.bf16x2.f32 %0, %1, %2;" : "=r"(r) : "f"(hi), "f"(lo));
    return r;
}
static __device__ __forceinline__ void split2(float v0, float v1, uint32_t& ph, uint32_t& pl) {
    __nv_bfloat16 h0 = __float2bfloat16_rn(v0), h1 = __float2bfloat16_rn(v1);
    float l0 = v0 - __bfloat162float(h0);
    float l1 = v1 - __bfloat162float(h1);
    ph = ((uint32_t)__bfloat16_as_ushort(h1) << 16) | (uint32_t)__bfloat16_as_ushort(h0);
    pl = packbf(l0, l1);
}
static __device__ __forceinline__ void cpa16(void* dst, const void* src) {
    uint32_t d = smem_u32(dst);
    asm volatile("cp.async.cg.shared.global [%0], [%1], 16;\n" :: "r"(d), "l"(src));
}
static __device__ __forceinline__ void cpacommit() {
    asm volatile("cp.async.commit_group;\n");
}
template <int N>
static __device__ __forceinline__ void cpawait() {
    asm volatile("cp.async.wait_group %0;\n" :: "n"(N));
}
static __device__ __forceinline__ uint32_t ht_hash(uint32_t k) {
    return (k * 2654435761u) & HT_MASK;
}

// ---------------- single-kernel matching + compaction (1 block, 1024 threads) ----------------
__global__ void match_all_k(const int* __restrict__ pe, const int* __restrict__ pa) {
    int t = threadIdx.x;
    // phase 1: clear hash table
#pragma unroll
    for (int i = t; i < HT_SIZE; i += 1024) d_ht[i] = HT_EMPTY;
    __syncthreads();
    // phase 2: insert agents
#pragma unroll
    for (int j = t; j < LA; j += 1024) {
        d_unmatched[j] = 1;
        uint32_t key = (uint32_t)pa[j];
        unsigned long long entry = ((unsigned long long)key << 32) | (uint32_t)j;
        uint32_t h = ht_hash(key);
        while (true) {
            unsigned long long prev = atomicCAS(&d_ht[h], HT_EMPTY, entry);
            if (prev == HT_EMPTY) break;
            h = (h + 1) & HT_MASK;
        }
    }
    __syncthreads();
    // phase 3: ego lookup
#pragma unroll
    for (int i = t; i < LE; i += 1024) {
        uint32_t key = (uint32_t)pe[i];
        uint32_t h = ht_hash(key);
        int m = 0, a = 0;
        while (true) {
            unsigned long long e = d_ht[h];
            if (e == HT_EMPTY) break;
            if ((uint32_t)(e >> 32) == key) { m = 1; a = (int)(uint32_t)e; break; }
            h = (h + 1) & HT_MASK;
        }
        d_matched[i] = m;
        d_afe[i] = a;
        if (m) d_unmatched[a] = 0;   // bijection on unique values
    }
    __syncthreads();
    // phase 4: exclusive-scan compaction of unmatched agents
    __shared__ int wsum[32];
    int f0 = d_unmatched[2 * t], f1 = d_unmatched[2 * t + 1];
    int s = f0 + f1;
    int lane = t & 31, w = t >> 5;
    int v = s;
#pragma unroll
    for (int o = 1; o < 32; o <<= 1) {
        int n = __shfl_up_sync(0xffffffffu, v, o);
        if (lane >= o) v += n;
    }
    if (lane == 31) wsum[w] = v;
    __syncthreads();
    if (w == 0) {
        int x = wsum[lane];
#pragma unroll
        for (int o = 1; o < 32; o <<= 1) {
            int n = __shfl_up_sync(0xffffffffu, x, o);
            if (lane >= o) x += n;
        }
        wsum[lane] = x;
    }
    __syncthreads();
    int base = (w > 0 ? wsum[w - 1] : 0) + (v - s);
    if (f0) d_remain[base] = 2 * t;
    if (f1) d_remain[base + f0] = 2 * t + 1;
}

// ---------------- one-shot weight split ----------------
struct WS {
    const float* s[7];
    __nv_bfloat16* h[7];
    __nv_bfloat16* l[7];
    int off[8];
};
__global__ void wsplit_k(WS ws) {
    int i = blockIdx.x * blockDim.x + threadIdx.x;
    int r = 0;
#pragma unroll
    for (int j = 1; j < 7; j++)
        if (i >= ws.off[j]) r = j;
    int loc = i - ws.off[r];
    float v = ws.s[r][loc];
    __nv_bfloat16 hh = __float2bfloat16_rn(v);
    ws.h[r][loc] = hh;
    ws.l[r][loc] = __float2bfloat16_rn(v - __bfloat162float(hh));
}

// ---------------- fused builds ----------------
__global__ void build_fusedin_k(const float* __restrict__ xe, const float* __restrict__ xa) {
    int idx = blockIdx.x * blockDim.x + threadIdx.x;
    if (idx >= LE * 2 * CM) return;
    int row = idx >> 9;
    int c = idx & 511;
    float v = (c < CM) ? xe[row * CM + c] : xa[d_afe[row] * CM + (c - CM)];
    __nv_bfloat16 hh = __float2bfloat16_rn(v);
    b_fi_h[idx] = hh;
    b_fi_l[idx] = __float2bfloat16_rn(v - __bfloat162float(hh));
}
__global__ void build_q_k(const float* __restrict__ xe, const float* __restrict__ xa) {
    int idx = blockIdx.x * blockDim.x + threadIdx.x;
    if (idx >= LQ * CM) return;
    int row = idx >> 8;
    int c = idx & 255;
    float v;
    if (row < LE) v = d_matched[row] ? d_fused[idx] : xe[idx];
    else v = xa[d_remain[row - LE] * CM + c];
    d_q[idx] = v;
    __nv_bfloat16 hh = __float2bfloat16_rn(v);
    b_q_h[idx] = hh;
    b_q_l[idx] = __float2bfloat16_rn(v - __bfloat162float(hh));
}
__global__ void build_kv_k(const float* __restrict__ xe, const float* __restrict__ xa) {
    int idx = blockIdx.x * blockDim.x + threadIdx.x;
    if (idx >= LK * CM) return;
    int row = idx >> 8;
    float v = (row < LE) ? xe[idx] : xa[idx - LE * CM];
    __nv_bfloat16 hh = __float2bfloat16_rn(v);
    b_kv_h[idx] = hh;
    b_kv_l[idx] = __float2bfloat16_rn(v - __bfloat162float(hh));
}

// ---------------- output-mode codes ----------------
#define OUT_F32 0
#define OUT_SPLIT 1
#define OUT_BF16 2
#define OUT_KV 3

// common epilogue for a 16-row pair owned by one thread
template <int OMODE, bool RELU, bool RESID>
static __device__ __forceinline__ void epi_store(
    float* acc4, int r0, int col, int N,
    const float* __restrict__ bias, const float* __restrict__ Rm,
    float* __restrict__ Cf, __nv_bfloat16* __restrict__ Ch, __nv_bfloat16* __restrict__ Cl) {
    float b0 = bias[col], b1 = bias[col + 1];
    float v0 = acc4[0] + b0, v1 = acc4[1] + b1;
    float v2 = acc4[2] + b0, v3 = acc4[3] + b1;
    if (RESID) {
        v0 += Rm[(size_t)r0 * N + col];       v1 += Rm[(size_t)r0 * N + col + 1];
        v2 += Rm[(size_t)(r0 + 8) * N + col]; v3 += Rm[(size_t)(r0 + 8) * N + col + 1];
    }
    if (RELU) {
        v0 = fmaxf(v0, 0.f); v1 = fmaxf(v1, 0.f);
        v2 = fmaxf(v2, 0.f); v3 = fmaxf(v3, 0.f);
    }
    size_t i0 = (size_t)r0 * N + col, i1 = (size_t)(r0 + 8) * N + col;
    if (OMODE == OUT_F32) {
        *(float2*)&Cf[i0] = make_float2(v0, v1);
        *(float2*)&Cf[i1] = make_float2(v2, v3);
    } else if (OMODE == OUT_BF16) {
        *(uint32_t*)&Ch[i0] = packbf(v0, v1);
        *(uint32_t*)&Ch[i1] = packbf(v2, v3);
    } else if (OMODE == OUT_SPLIT) {
        uint32_t ph, pl;
        split2(v0, v1, ph, pl);
        *(uint32_t*)&Ch[i0] = ph; *(uint32_t*)&Cl[i0] = pl;
        split2(v2, v3, ph, pl);
        *(uint32_t*)&Ch[i1] = ph; *(uint32_t*)&Cl[i1] = pl;
    } else {  // OUT_KV
        __nv_bfloat16* dst = (col < CM) ? Ch : Cl;
        int cc = col & (CM - 1);
        *(uint32_t*)&dst[(size_t)r0 * CM + cc] = packbf(v0, v1);
        *(uint32_t*)&dst[(size_t)(r0 + 8) * CM + cc] = packbf(v2, v3);
    }
}

// ---------------- split-bf16 GEMM, BM=64 (small-M / deep-K shapes) ----------------
template <int OMODE, bool RELU, bool RESID>
__global__ void gemm_bs_k(const __nv_bfloat16* __restrict__ Ah, const __nv_bfloat16* __restrict__ Al,
                          const __nv_bfloat16* __restrict__ Wh, const __nv_bfloat16* __restrict__ Wl,
                          const float* __restrict__ bias, const float* __restrict__ Rm,
                          float* __restrict__ Cf, __nv_bfloat16* __restrict__ Ch,
                          __nv_bfloat16* __restrict__ Cl, int M, int N, int K) {
    __shared__ __nv_bfloat16 As[2][2][64][40];
    __shared__ __nv_bfloat16 Ws[2][2][64][40];
    int tid = threadIdx.x, lane = tid & 31, wid = tid >> 5;
    int bm = blockIdx.y << 6, bn = blockIdx.x << 6;
    int wm = (wid >> 1) << 4, wn = (wid & 1) << 5;

    float acc[4][4];
#pragma unroll
    for (int j = 0; j < 4; j++)
#pragma unroll
        for (int k = 0; k < 4; k++) acc[j][k] = 0.f;

    int lr = tid >> 2;
    int lc = (tid & 3) << 3;
    const __nv_bfloat16* gAh = Ah + (size_t)(bm + lr) * K + lc;
    const __nv_bfloat16* gAl = Al + (size_t)(bm + lr) * K + lc;
    const __nv_bfloat16* gWh = Wh + (size_t)(bn + lr) * K + lc;
    const __nv_bfloat16* gWl = Wl + (size_t)(bn + lr) * K + lc;

    int a_r = lane & 15, a_c = (lane >> 4) << 3;
    int b_r = (lane & 7) + ((lane >> 4) << 3), b_c = ((lane >> 3) & 1) << 3;
    int KT = K >> 5;

    {
        cpa16(&As[0][0][lr][lc], gAh);
        cpa16(&As[0][1][lr][lc], gAl);
        cpa16(&Ws[0][0][lr][lc], gWh);
        cpa16(&Ws[0][1][lr][lc], gWl);
        cpacommit();
    }

    for (int kt = 0; kt < KT; kt++) {
        int cur = kt & 1;
        if (kt + 1 < KT) {
            int k0 = (kt + 1) << 5;
            int nx = cur ^ 1;
            cpa16(&As[nx][0][lr][lc], gAh + k0);
            cpa16(&As[nx][1][lr][lc], gAl + k0);
            cpa16(&Ws[nx][0][lr][lc], gWh + k0);
            cpa16(&Ws[nx][1][lr][lc], gWl + k0);
            cpacommit();
            cpawait<1>();
        } else {
            cpawait<0>();
        }
        __syncthreads();
#pragma unroll
        for (int ks = 0; ks < 2; ks++) {
            uint32_t ah[4], al[4], bh[4][2], bl[4][2];
            ldm4(ah, &As[cur][0][wm + a_r][(ks << 4) + a_c]);
            ldm4(al, &As[cur][1][wm + a_r][(ks << 4) + a_c]);
#pragma unroll
            for (int np = 0; np < 2; np++) {
                uint32_t t4[4];
                ldm4(t4, &Ws[cur][0][wn + (np << 4) + b_r][(ks << 4) + b_c]);
                bh[np * 2][0] = t4[0]; bh[np * 2][1] = t4[1];
                bh[np * 2 + 1][0] = t4[2]; bh[np * 2 + 1][1] = t4[3];
                ldm4(t4, &Ws[cur][1][wn + (np << 4) + b_r][(ks << 4) + b_c]);
                bl[np * 2][0] = t4[0]; bl[np * 2][1] = t4[1];
                bl[np * 2 + 1][0] = t4[2]; bl[np * 2 + 1][1] = t4[3];
            }
#pragma unroll
            for (int nt = 0; nt < 4; nt++) {
                mma_bf16(acc[nt], ah, bh[nt]);
                mma_bf16(acc[nt], ah, bl[nt]);
                mma_bf16(acc[nt], al, bh[nt]);
            }
        }
        __syncthreads();
    }

    int g = lane >> 2, qd = lane & 3;
    int r0 = bm + wm + g;
#pragma unroll
    for (int nt = 0; nt < 4; nt++) {
        int col = bn + wn + (nt << 3) + (qd << 1);
        epi_store<OMODE, RELU, RESID>(acc[nt], r0, col, N, bias, Rm, Cf, Ch, Cl);
    }
}

// ---------------- split-bf16 GEMM, BM=128, warp tile 32x32, BK=16 (large GEMMs) ----------------
template <int OMODE, bool RELU, bool RESID>
__global__ void gemm128_bs_k(const __nv_bfloat16* __restrict__ Ah, const __nv_bfloat16* __restrict__ Al,
                             const __nv_bfloat16* __restrict__ Wh, const __nv_bfloat16* __restrict__ Wl,
                             const float* __restrict__ bias, const float* __restrict__ Rm,
                             float* __restrict__ Cf, __nv_bfloat16* __restrict__ Ch,
                             __nv_bfloat16* __restrict__ Cl, int M, int N, int K) {
    __shared__ __nv_bfloat16 As[2][2][128][24];   // [stage][hi/lo][row][16+8 pad]
    __shared__ __nv_bfloat16 Ws[2][2][64][24];
    int tid = threadIdx.x, lane = tid & 31, wid = tid >> 5;
    int bm = blockIdx.y << 7, bn = blockIdx.x << 6;
    int wm = (wid >> 1) << 5, wn = (wid & 1) << 5;

    float acc[2][4][4];
#pragma unroll
    for (int i = 0; i < 2; i++)
#pragma unroll
        for (int j = 0; j < 4; j++)
#pragma unroll
            for (int k = 0; k < 4; k++) acc[i][j][k] = 0.f;

    int ar = tid >> 1, ac = (tid & 1) << 3;                 // A tile 128x16
    int wsel = tid >> 7;                                    // 0: Wh, 1: Wl
    int wr = (tid & 127) >> 1, wc = (tid & 1) << 3;         // W tile 64x16
    const __nv_bfloat16* gAh = Ah + (size_t)(bm + ar) * K + ac;
    const __nv_bfloat16* gAl = Al + (size_t)(bm + ar) * K + ac;
    const __nv_bfloat16* gW = (wsel ? Wl : Wh) + (size_t)(bn + wr) * K + wc;

    int a_r = lane & 15, a_c = (lane >> 4) << 3;
    int b_r = (lane & 7) + ((lane >> 4) << 3), b_c = ((lane >> 3) & 1) << 3;
    int KT = K >> 4;

    {
        cpa16(&As[0][0][ar][ac], gAh);
        cpa16(&As[0][1][ar][ac], gAl);
        cpa16(&Ws[0][wsel][wr][wc], gW);
        cpacommit();
    }

    for (int kt = 0; kt < KT; kt++) {
        int cur = kt & 1;
        if (kt + 1 < KT) {
            int k0 = (kt + 1) << 4;
            int nx = cur ^ 1;
            cpa16(&As[nx][0][ar][ac], gAh + k0);
            cpa16(&As[nx][1][ar][ac], gAl + k0);
            cpa16(&Ws[nx][wsel][wr][wc], gW + k0);
            cpacommit();
            cpawait<1>();
        } else {
            cpawait<0>();
        }
        __syncthreads();
        {
            uint32_t ah[2][4], al[2][4], bh[4][2], bl[4][2];
#pragma unroll
            for (int mt = 0; mt < 2; mt++) {
                ldm4(ah[mt], &As[cur][0][wm + (mt << 4) + a_r][a_c]);
                ldm4(al[mt], &As[cur][1][wm + (mt << 4) + a_r][a_c]);
            }
#pragma unroll
            for (int np = 0; np < 2; np++) {
                uint32_t t4[4];
                ldm4(t4, &Ws[cur][0][wn + (np << 4) + b_r][b_c]);
                bh[np * 2][0] = t4[0]; bh[np * 2][1] = t4[1];
                bh[np * 2 + 1][0] = t4[2]; bh[np * 2 + 1][1] = t4[3];
                ldm4(t4, &Ws[cur][1][wn + (np << 4) + b_r][b_c]);
                bl[np * 2][0] = t4[0]; bl[np * 2][1] = t4[1];
                bl[np * 2 + 1][0] = t4[2]; bl[np * 2 + 1][1] = t4[3];
            }
#pragma unroll
            for (int mt = 0; mt < 2; mt++)
#pragma unroll
                for (int nt = 0; nt < 4; nt++) {
                    mma_bf16(acc[mt][nt], ah[mt], bh[nt]);
                    mma_bf16(acc[mt][nt], ah[mt], bl[nt]);
                    mma_bf16(acc[mt][nt], al[mt], bh[nt]);
                }
        }
        __syncthreads();
    }

    int g = lane >> 2, qd = lane & 3;
#pragma unroll
    for (int mt = 0; mt < 2; mt++) {
        int r0 = bm + wm + (mt << 4) + g;
#pragma unroll
        for (int nt = 0; nt < 4; nt++) {
            int col = bn + wn + (nt << 3) + (qd << 1);
            epi_store<OMODE, RELU, RESID>(acc[mt][nt], r0, col, N, bias, Rm, Cf, Ch, Cl);
        }
    }
}

// ---------------- flash attention: 128 queries/block, 256 threads, cp.async kv pipeline ----------------
__global__ void attn_mma_k(const __nv_bfloat16* __restrict__ Qb, const __nv_bfloat16* __restrict__ Kb,
                           const __nv_bfloat16* __restrict__ Vb,
                           __nv_bfloat16* __restrict__ Oh, __nv_bfloat16* __restrict__ Ol) {
    __shared__ __nv_bfloat16 Qs[128][40];
    __shared__ __nv_bfloat16 Ks[2][64][40];
    __shared__ __nv_bfloat16 Vs[2][64][40];
    int tid = threadIdx.x, lane = tid & 31, wid = tid >> 5;
    int h = blockIdx.y, q0 = blockIdx.x << 7;
    int hc = h << 5;

    int kvr = tid >> 2, kvc = (tid & 3) << 3;   // kv tile loader: 64 rows x 32
    {
        const __nv_bfloat16* pk = Kb + (size_t)kvr * CM + hc + kvc;
        const __nv_bfloat16* pv = Vb + (size_t)kvr * CM + hc + kvc;
        cpa16(&Ks[0][kvr][kvc], pk);
        cpa16(&Vs[0][kvr][kvc], pv);
        cpacommit();
    }
    {
        int r = tid >> 1, c = (tid & 1) << 4;   // Q: 128 rows x 32
        const uint4* p = (const uint4*)(Qb + (size_t)(q0 + r) * CM + hc + c);
        *(uint4*)&Qs[r][c] = p[0];
        *(uint4*)&Qs[r][c + 8] = p[1];
    }
    __syncthreads();

    int a_r = lane & 15, a_c = (lane >> 4) << 3;
    uint32_t qf[2][4];
    ldm4(qf[0], &Qs[(wid << 4) + a_r][a_c]);
    ldm4(qf[1], &Qs[(wid << 4) + a_r][16 + a_c]);

    float o[4][4];
#pragma unroll
    for (int i = 0; i < 4; i++)
#pragma unroll
        for (int j = 0; j < 4; j++) o[i][j] = 0.f;
    float m0 = -1e30f, m1 = -1e30f, l0 = 0.f, l1 = 0.f;

    int b_r = (lane & 7) + ((lane >> 4) << 3), b_c = ((lane >> 3) & 1) << 3;
    int NT = LK / 64;

    for (int t = 0; t < NT; t++) {
        int cur = t & 1;
        if (t + 1 < NT) {
            int nx = cur ^ 1;
            const __nv_bfloat16* pk = Kb + (size_t)((t + 1) * 64 + kvr) * CM + hc + kvc;
            const __nv_bfloat16* pv = Vb + (size_t)((t + 1) * 64 + kvr) * CM + hc + kvc;
            cpa16(&Ks[nx][kvr][kvc], pk);
            cpa16(&Vs[nx][kvr][kvc], pv);
            cpacommit();
            cpawait<1>();
        } else {
            cpawait<0>();
        }
        __syncthreads();

        float s[8][4];
#pragma unroll
        for (int j = 0; j < 8; j++)
#pragma unroll
            for (int c = 0; c < 4; c++) s[j][c] = 0.f;
#pragma unroll
        for (int ks = 0; ks < 2; ks++) {
#pragma unroll
            for (int jp = 0; jp < 4; jp++) {
                uint32_t t4[4];
                ldm4(t4, &Ks[cur][(jp << 4) + b_r][(ks << 4) + b_c]);
                uint32_t bb0[2] = {t4[0], t4[1]};
                uint32_t bb1[2] = {t4[2], t4[3]};
                mma_bf16(s[jp * 2], qf[ks], bb0);
                mma_bf16(s[jp * 2 + 1], qf[ks], bb1);
            }
        }
#pragma unroll
        for (int j = 0; j < 8; j++) {
            s[j][0] *= SCALE; s[j][1] *= SCALE; s[j][2] *= SCALE; s[j][3] *= SCALE;
        }

        float rmax0 = -1e30f, rmax1 = -1e30f;
#pragma unroll
        for (int j = 0; j < 8; j++) {
            rmax0 = fmaxf(rmax0, fmaxf(s[j][0], s[j][1]));
            rmax1 = fmaxf(rmax1, fmaxf(s[j][2], s[j][3]));
        }
        rmax0 = fmaxf(rmax0, __shfl_xor_sync(0xffffffffu, rmax0, 1));
        rmax0 = fmaxf(rmax0, __shfl_xor_sync(0xffffffffu, rmax0, 2));
        rmax1 = fmaxf(rmax1, __shfl_xor_sync(0xffffffffu, rmax1, 1));
        rmax1 = fmaxf(rmax1, __shfl_xor_sync(0xffffffffu, rmax1, 2));

        float mn0 = fmaxf(m0, rmax0), mn1 = fmaxf(m1, rmax1);
        float c0 = __expf(m0 - mn0), c1 = __expf(m1 - mn1);
        float sum0 = 0.f, sum1 = 0.f;
        uint32_t pa[4][4];
#pragma unroll
        for (int jj = 0; jj < 4; jj++) {
            float p00 = __expf(s[2 * jj][0] - mn0),     p01 = __expf(s[2 * jj][1] - mn0);
            float p02 = __expf(s[2 * jj][2] - mn1),     p03 = __expf(s[2 * jj][3] - mn1);
            float p10 = __expf(s[2 * jj + 1][0] - mn0), p11 = __expf(s[2 * jj + 1][1] - mn0);
            float p12 = __expf(s[2 * jj + 1][2] - mn1), p13 = __expf(s[2 * jj + 1][3] - mn1);
            sum0 += p00 + p01 + p10 + p11;
            sum1 += p02 + p03 + p12 + p13;
            pa[jj][0] = packbf(p00, p01);
            pa[jj][1] = packbf(p02, p03);
            pa[jj][2] = packbf(p10, p11);
            pa[jj][3] = packbf(p12, p13);
        }
        sum0 += __shfl_xor_sync(0xffffffffu, sum0, 1);
        sum0 += __shfl_xor_sync(0xffffffffu, sum0, 2);
        sum1 += __shfl_xor_sync(0xffffffffu, sum1, 1);
        sum1 += __shfl_xor_sync(0xffffffffu, sum1, 2);
        l0 = l0 * c0 + sum0;
        l1 = l1 * c1 + sum1;
        m0 = mn0; m1 = mn1;
#pragma unroll
        for (int nt = 0; nt < 4; nt++) {
            o[nt][0] *= c0; o[nt][1] *= c0; o[nt][2] *= c1; o[nt][3] *= c1;
        }

#pragma unroll
        for (int jj = 0; jj < 4; jj++) {
            uint32_t t4[4];
            ldm4t(t4, &Vs[cur][(jj << 4) + (lane & 15)][(lane >> 4) << 3]);
            {
                uint32_t bb0[2] = {t4[0], t4[1]};
                uint32_t bb1[2] = {t4[2], t4[3]};
                mma_bf16(o[0], pa[jj], bb0);
                mma_bf16(o[1], pa[jj], bb1);
            }
            ldm4t(t4, &Vs[cur][(jj << 4) + (lane & 15)][16 + ((lane >> 4) << 3)]);
            {
                uint32_t bb0[2] = {t4[0], t4[1]};
                uint32_t bb1[2] = {t4[2], t4[3]};
                mma_bf16(o[2], pa[jj], bb0);
                mma_bf16(o[3], pa[jj], bb1);
            }
        }
        __syncthreads();
    }

    float inv0 = 1.f / l0, inv1 = 1.f / l1;
    int g = lane >> 2, qd = lane & 3;
    int row0 = q0 + (wid << 4) + g;
#pragma unroll
    for (int nt = 0; nt < 4; nt++) {
        int col = hc + (nt << 3) + (qd << 1);
        uint32_t ph, pl;
        split2(o[nt][0] * inv0, o[nt][1] * inv0, ph, pl);
        *(uint32_t*)&Oh[(size_t)row0 * CM + col] = ph;
        *(uint32_t*)&Ol[(size_t)row0 * CM + col] = pl;
        split2(o[nt][2] * inv1, o[nt][3] * inv1, ph, pl);
        *(uint32_t*)&Oh[(size_t)(row0 + 8) * CM + col] = ph;
        *(uint32_t*)&Ol[(size_t)(row0 + 8) * CM + col] = pl;
    }
}

// ---------------- LayerNorm ----------------
template <bool SPLIT>
__global__ void ln_k(const float* __restrict__ X, const float* __restrict__ g,
                     const float* __restrict__ b, float* __restrict__ Y,
                     __nv_bfloat16* __restrict__ Yh, __nv_bfloat16* __restrict__ Yl) {
    int row = blockIdx.x;
    int c = threadIdx.x;
    float v = X[row * CM + c];
    float s = v, s2 = v * v;
#pragma unroll
    for (int o = 16; o > 0; o >>= 1) {
        s += __shfl_xor_sync(0xffffffffu, s, o);
        s2 += __shfl_xor_sync(0xffffffffu, s2, o);
    }
    __shared__ float rs[8], rs2[8];
    int w = c >> 5, lane = c & 31;
    if (lane == 0) { rs[w] = s; rs2[w] = s2; }
    __syncthreads();
    float tot = 0.f, tot2 = 0.f;
#pragma unroll
    for (int i = 0; i < 8; i++) { tot += rs[i]; tot2 += rs2[i]; }
    float mean = tot * (1.f / 256.f);
    float var = tot2 * (1.f / 256.f) - mean * mean;
    float is = rsqrtf(var + 1e-5f);
    float y = (v - mean) * is * g[c] + b[c];
    Y[row * CM + c] = y;
    if (SPLIT) {
        __nv_bfloat16 hh = __float2bfloat16_rn(y);
        Yh[row * CM + c] = hh;
        Yl[row * CM + c] = __float2bfloat16_rn(y - __bfloat162float(hh));
    }
}

// ---------------- launcher ----------------
#define SYM(p, s) cudaGetSymbolAddress((void**)&p, s)

extern "C" void kernel_launch(void* const* d_in, const int* in_sizes, int n_in,
                              void* d_out, int out_size) {
    const float* x_ego  = (const float*)d_in[0];
    const float* x_agent = (const float*)d_in[1];
    const float* Wf1 = (const float*)d_in[2];
    const float* bf1 = (const float*)d_in[3];
    const float* Wf2 = (const float*)d_in[4];
    const float* bf2 = (const float*)d_in[5];
    const float* Wf3 = (const float*)d_in[6];
    const float* bf3 = (const float*)d_in[7];
    const float* Wqkv = (const float*)d_in[8];
    const float* bqkv = (const float*)d_in[9];
    const float* Wo = (const float*)d_in[10];
    const float* bo = (const float*)d_in[11];
    const float* W1 = (const float*)d_in[12];
    const float* b1 = (const float*)d_in[13];
    const float* W2 = (const float*)d_in[14];
    const float* b2 = (const float*)d_in[15];
    const float* g1 = (const float*)d_in[16];
    const float* be1 = (const float*)d_in[17];
    const float* g2 = (const float*)d_in[18];
    const float* be2 = (const float*)d_in[19];
    const int* pos_ego = (const int*)d_in[20];
    const int* pos_agent = (const int*)d_in[21];
    float* out = (float*)d_out;

    float *p_fused, *p_q, *p_res1, *p_yq, *p_res2;
    SYM(p_fused, d_fused); SYM(p_q, d_q); SYM(p_res1, d_res1);
    SYM(p_yq, d_yq); SYM(p_res2, d_res2);

    __nv_bfloat16 *fi_h, *fi_l, *h1_h, *h1_l, *h2_h, *h2_l, *q_h, *q_l, *kv_h, *kv_l;
    __nv_bfloat16 *Qb, *Kb, *Vb, *at_h, *at_l, *yq_h, *yq_l, *ff_h, *ff_l;
    __nv_bfloat16 *wf1_h, *wf1_l, *wf2_h, *wf2_l, *wf3_h, *wf3_l;
    __nv_bfloat16 *wqkv_h, *wqkv_l, *wo_h, *wo_l, *w1_h, *w1_l, *w2_h, *w2_l;
    SYM(fi_h, b_fi_h); SYM(fi_l, b_fi_l);
    SYM(h1_h, b_h1_h); SYM(h1_l, b_h1_l);
    SYM(h2_h, b_h2_h); SYM(h2_l, b_h2_l);
    SYM(q_h, b_q_h); SYM(q_l, b_q_l);
    SYM(kv_h, b_kv_h); SYM(kv_l, b_kv_l);
    SYM(Qb, b_Q); SYM(Kb, b_K); SYM(Vb, b_V);
    SYM(at_h, b_at_h); SYM(at_l, b_at_l);
    SYM(yq_h, b_yq_h); SYM(yq_l, b_yq_l);
    SYM(ff_h, b_ff_h); SYM(ff_l, b_ff_l);
    SYM(wf1_h, b_wf1_h); SYM(wf1_l, b_wf1_l);
    SYM(wf2_h, b_wf2_h); SYM(wf2_l, b_wf2_l);
    SYM(wf3_h, b_wf3_h); SYM(wf3_l, b_wf3_l);
    SYM(wqkv_h, b_wqkv_h); SYM(wqkv_l, b_wqkv_l);
    SYM(wo_h, b_wo_h); SYM(wo_l, b_wo_l);
    SYM(w1_h, b_w1_h); SYM(w1_l, b_w1_l);
    SYM(w2_h, b_w2_h); SYM(w2_l, b_w2_l);

    static cudaStream_t sA = nullptr, sB = nullptr;
    static cudaEvent_t ev0, ev1, ev2;
    if (!sA) {
        cudaStreamCreateWithFlags(&sA, cudaStreamNonBlocking);
        cudaStreamCreateWithFlags(&sB, cudaStreamNonBlocking);
        cudaEventCreateWithFlags(&ev0, cudaEventDisableTiming);
        cudaEventCreateWithFlags(&ev1, cudaEventDisableTiming);
        cudaEventCreateWithFlags(&ev2, cudaEventDisableTiming);
    }

    WS ws;
    ws.s[0] = Wf1;  ws.h[0] = wf1_h;  ws.l[0] = wf1_l;
    ws.s[1] = Wf2;  ws.h[1] = wf2_h;  ws.l[1] = wf2_l;
    ws.s[2] = Wf3;  ws.h[2] = wf3_h;  ws.l[2] = wf3_l;
    ws.s[3] = Wqkv; ws.h[3] = wqkv_h; ws.l[3] = wqkv_l;
    ws.s[4] = Wo;   ws.h[4] = wo_h;   ws.l[4] = wo_l;
    ws.s[5] = W1;   ws.h[5] = w1_h;   ws.l[5] = w1_l;
    ws.s[6] = W2;   ws.h[6] = w2_h;   ws.l[6] = w2_l;
    ws.off[0] = 0;       ws.off[1] = 131072;  ws.off[2] = 196608; ws.off[3] = 262144;
    ws.off[4] = 458752;  ws.off[5] = 524288;  ws.off[6] = 786432; ws.off[7] = 1048576;

    // fork point
    cudaEventRecord(ev0, 0);

    // branch A: weight splits
    cudaStreamWaitEvent(sA, ev0, 0);
    wsplit_k<<<4096, 256, 0, sA>>>(ws);
    cudaEventRecord(ev1, sA);

    // branch B: kv build + K/V projection
    cudaStreamWaitEvent(sB, ev0, 0);
    build_kv_k<<<(LK * CM) / 256, 256, 0, sB>>>(x_ego, x_agent);
    cudaStreamWaitEvent(sB, ev1, 0);
    gemm128_bs_k<OUT_KV, false, false><<<dim3(2 * CM / 64, LK / 128), 256, 0, sB>>>(
        kv_h, kv_l, wqkv_h + CM * CM, wqkv_l + CM * CM, bqkv + CM, nullptr,
        nullptr, Kb, Vb, LK, 2 * CM, CM);
    cudaEventRecord(ev2, sB);

    // main branch: matching, fusion MLP, Q path
    match_all_k<<<1, 1024>>>(pos_ego, pos_agent);
    build_fusedin_k<<<(LE * 2 * CM) / 256, 256>>>(x_ego, x_agent);
    cudaStreamWaitEvent(0, ev1, 0);
    gemm_bs_k<OUT_SPLIT, true, false><<<dim3(CM / 64, LE / 64), 256>>>(
        fi_h, fi_l, wf1_h, wf1_l, bf1, nullptr, nullptr, h1_h, h1_l, LE, CM, 2 * CM);
    gemm_bs_k<OUT_SPLIT, true, false><<<dim3(CM / 64, LE / 64), 256>>>(
        h1_h, h1_l, wf2_h, wf2_l, bf2, nullptr, nullptr, h2_h, h2_l, LE, CM, CM);
    gemm_bs_k<OUT_F32, false, false><<<dim3(CM / 64, LE / 64), 256>>>(
        h2_h, h2_l, wf3_h, wf3_l, bf3, nullptr, p_fused, nullptr, nullptr, LE, CM, CM);
    build_q_k<<<(LQ * CM) / 256, 256>>>(x_ego, x_agent);
    gemm_bs_k<OUT_BF16, false, false><<<dim3(CM / 64, LQ / 64), 256>>>(
        q_h, q_l, wqkv_h, wqkv_l, bqkv, nullptr, nullptr, Qb, nullptr, LQ, CM, CM);

    // join: attention needs K/V
    cudaStreamWaitEvent(0, ev2, 0);
    attn_mma_k<<<dim3(LQ / 128, HN), 256>>>(Qb, Kb, Vb, at_h, at_l);

    gemm_bs_k<OUT_F32, false, true><<<dim3(CM / 64, LQ / 64), 256>>>(
        at_h, at_l, wo_h, wo_l, bo, p_q, p_res1, nullptr, nullptr, LQ, CM, CM);
    ln_k<true><<<LQ, 256>>>(p_res1, g1, be1, p_yq, yq_h, yq_l);
    gemm128_bs_k<OUT_SPLIT, true, false><<<dim3(DF / 64, LQ / 128), 256>>>(
        yq_h, yq_l, w1_h, w1_l, b1, nullptr, nullptr, ff_h, ff_l, LQ, DF, CM);
    gemm_bs_k<OUT_F32, false, true><<<dim3(CM / 64, LQ / 64), 256>>>(
        ff_h, ff_l, w2_h, w2_l, b2, p_yq, p_res2, nullptr, nullptr, LQ, CM, DF);
    ln_k<false><<<LQ, 256>>>(p_res2, g2, be2, out, nullptr, nullptr);
}

// round 11
// speedup vs baseline: 1.0727x; 1.0727x over previous
#include <cuda_runtime.h>
#include <cuda_bf16.h>
#include <cstdint>

// ---------------- problem constants ----------------
#define LE 2048
#define LA 2048
#define CM 256          // d_model
#define HN 8            // heads
#define DH 32           // head dim
#define DF 1024         // ffn dim
#define LQ 3072         // 2048 + 1024 remain
#define LK 4096         // 2048 + 2048
#define SCALE 0.17677669529663687f   // 1/sqrt(32)

#define HT_SIZE 4096
#define HT_MASK (HT_SIZE - 1)
#define HT_EMPTY 0xFFFFFFFFFFFFFFFFull

// ---------------- fp32 scratch ----------------
__device__ float d_q[LQ * CM];
__device__ float d_res1[LQ * CM];
__device__ float d_yq[LQ * CM];
__device__ float d_res2[LQ * CM];
__device__ int d_matched[LE];
__device__ int d_afe[LE];
__device__ int d_unmatched[LA];
__device__ int d_remain[LA];
__device__ unsigned long long d_ht[HT_SIZE];

// ---------------- bf16 scratch ----------------
__device__ __nv_bfloat16 b_fi_h[LE * 2 * CM], b_fi_l[LE * 2 * CM];
__device__ __nv_bfloat16 b_h1_h[LE * CM], b_h1_l[LE * CM];
__device__ __nv_bfloat16 b_h2_h[LE * CM], b_h2_l[LE * CM];
__device__ __nv_bfloat16 b_q_h[LQ * CM], b_q_l[LQ * CM];
__device__ __nv_bfloat16 b_kv_h[LK * CM], b_kv_l[LK * CM];
__device__ __nv_bfloat16 b_Q[LQ * CM];
__device__ __nv_bfloat16 b_K[LK * CM];
__device__ __nv_bfloat16 b_V[LK * CM];
__device__ __nv_bfloat16 b_at_h[LQ * CM], b_at_l[LQ * CM];
__device__ __nv_bfloat16 b_yq_h[LQ * CM], b_yq_l[LQ * CM];
__device__ __nv_bfloat16 b_ff_h[LQ * DF], b_ff_l[LQ * DF];
__device__ __nv_bfloat16 b_wf1_h[CM * 2 * CM], b_wf1_l[CM * 2 * CM];
__device__ __nv_bfloat16 b_wf2_h[CM * CM], b_wf2_l[CM * CM];
__device__ __nv_bfloat16 b_wf3_h[CM * CM], b_wf3_l[CM * CM];
__device__ __nv_bfloat16 b_wqkv_h[3 * CM * CM], b_wqkv_l[3 * CM * CM];
__device__ __nv_bfloat16 b_wo_h[CM * CM], b_wo_l[CM * CM];
__device__ __nv_bfloat16 b_w1_h[DF * CM], b_w1_l[DF * CM];
__device__ __nv_bfloat16 b_w2_h[CM * DF], b_w2_l[CM * DF];

// ---------------- helpers ----------------
static __device__ __forceinline__ uint32_t smem_u32(const void* p) {
    return (uint32_t)__cvta_generic_to_shared(p);
}
static __device__ __forceinline__ void ldm4(uint32_t* r, const void* p) {
    uint32_t a = smem_u32(p);
    asm volatile("ldmatrix.sync.aligned.m8n8.x4.shared.b16 {%0,%1,%2,%3}, [%4];\n"
                 : "=r"(r[0]), "=r"(r[1]), "=r"(r[2]), "=r"(r[3]) : "r"(a));
}
static __device__ __forceinline__ void ldm4t(uint32_t* r, const void* p) {
    uint32_t a = smem_u32(p);
    asm volatile("ldmatrix.sync.aligned.m8n8.x4.trans.shared.b16 {%0,%1,%2,%3}, [%4];\n"
                 : "=r"(r[0]), "=r"(r[1]), "=r"(r[2]), "=r"(r[3]) : "r"(a));
}
static __device__ __forceinline__ void mma_bf16(float* c, const uint32_t* a, const uint32_t* b) {
    asm volatile("mma.sync.aligned.m16n8k16.row.col.f32.bf16.bf16.f32 "
                 "{%0,%1,%2,%3}, {%4,%5,%6,%7}, {%8,%9}, {%0,%1,%2,%3};\n"
                 : "+f"(c[0]), "+f"(c[1]), "+f"(c[2]), "+f"(c[3])
                 : "r"(a[0]), "r"(a[1]), "r"(a[2]), "r"(a[3]), "r"(b[0]), "r"(b[1]));
}
static __device__ __forceinline__ uint32_t packbf(float lo, float hi) {
    uint32_t r;
    asm("cvt.rn.bf16x2.f32 %0, %1, %2;" : "=r"(r) : "f"(hi), "f"(lo));
    return r;
}
static __device__ __forceinline__ void split2(float v0, float v1, uint32_t& ph, uint32_t& pl) {
    __nv_bfloat16 h0 = __float2bfloat16_rn(v0), h1 = __float2bfloat16_rn(v1);
    float l0 = v0 - __bfloat162float(h0);
    float l1 = v1 - __bfloat162float(h1);
    ph = ((uint32_t)__bfloat16_as_ushort(h1) << 16) | (uint32_t)__bfloat16_as_ushort(h0);
    pl = packbf(l0, l1);
}
static __device__ __forceinline__ void cpa16(void* dst, const void* src) {
    uint32_t d = smem_u32(dst);
    asm volatile("cp.async.cg.shared.global [%0], [%1], 16;\n" :: "r"(d), "l"(src));
}
static __device__ __forceinline__ void cpacommit() {
    asm volatile("cp.async.commit_group;\n");
}
template <int N>
static __device__ __forceinline__ void cpawait() {
    asm volatile("cp.async.wait_group %0;\n" :: "n"(N));
}
static __device__ __forceinline__ uint32_t ht_hash(uint32_t k) {
    return (k * 2654435761u) & HT_MASK;
}

// ---------------- single-kernel matching + compaction (1 block, 1024 threads) ----------------
__global__ void match_all_k(const int* __restrict__ pe, const int* __restrict__ pa) {
    int t = threadIdx.x;
#pragma unroll
    for (int i = t; i < HT_SIZE; i += 1024) d_ht[i] = HT_EMPTY;
    __syncthreads();
#pragma unroll
    for (int j = t; j < LA; j += 1024) {
        d_unmatched[j] = 1;
        uint32_t key = (uint32_t)pa[j];
        unsigned long long entry = ((unsigned long long)key << 32) | (uint32_t)j;
        uint32_t h = ht_hash(key);
        while (true) {
            unsigned long long prev = atomicCAS(&d_ht[h], HT_EMPTY, entry);
            if (prev == HT_EMPTY) break;
            h = (h + 1) & HT_MASK;
        }
    }
    __syncthreads();
#pragma unroll
    for (int i = t; i < LE; i += 1024) {
        uint32_t key = (uint32_t)pe[i];
        uint32_t h = ht_hash(key);
        int m = 0, a = 0;
        while (true) {
            unsigned long long e = d_ht[h];
            if (e == HT_EMPTY) break;
            if ((uint32_t)(e >> 32) == key) { m = 1; a = (int)(uint32_t)e; break; }
            h = (h + 1) & HT_MASK;
        }
        d_matched[i] = m;
        d_afe[i] = a;
        if (m) d_unmatched[a] = 0;
    }
    __syncthreads();
    __shared__ int wsum[32];
    int f0 = d_unmatched[2 * t], f1 = d_unmatched[2 * t + 1];
    int s = f0 + f1;
    int lane = t & 31, w = t >> 5;
    int v = s;
#pragma unroll
    for (int o = 1; o < 32; o <<= 1) {
        int n = __shfl_up_sync(0xffffffffu, v, o);
        if (lane >= o) v += n;
    }
    if (lane == 31) wsum[w] = v;
    __syncthreads();
    if (w == 0) {
        int x = wsum[lane];
#pragma unroll
        for (int o = 1; o < 32; o <<= 1) {
            int n = __shfl_up_sync(0xffffffffu, x, o);
            if (lane >= o) x += n;
        }
        wsum[lane] = x;
    }
    __syncthreads();
    int base = (w > 0 ? wsum[w - 1] : 0) + (v - s);
    if (f0) d_remain[base] = 2 * t;
    if (f1) d_remain[base + f0] = 2 * t + 1;
}

// ---------------- one-shot weight split ----------------
struct WS {
    const float* s[7];
    __nv_bfloat16* h[7];
    __nv_bfloat16* l[7];
    int off[8];
};
__global__ void wsplit_k(WS ws) {
    int i = blockIdx.x * blockDim.x + threadIdx.x;
    int r = 0;
#pragma unroll
    for (int j = 1; j < 7; j++)
        if (i >= ws.off[j]) r = j;
    int loc = i - ws.off[r];
    float v = ws.s[r][loc];
    __nv_bfloat16 hh = __float2bfloat16_rn(v);
    ws.h[r][loc] = hh;
    ws.l[r][loc] = __float2bfloat16_rn(v - __bfloat162float(hh));
}

// ---------------- fused builds ----------------
__global__ void build_fusedin_k(const float* __restrict__ xe, const float* __restrict__ xa) {
    int idx = blockIdx.x * blockDim.x + threadIdx.x;
    if (idx >= LE * 2 * CM) return;
    int row = idx >> 9;
    int c = idx & 511;
    float v = (c < CM) ? xe[row * CM + c] : xa[d_afe[row] * CM + (c - CM)];
    __nv_bfloat16 hh = __float2bfloat16_rn(v);
    b_fi_h[idx] = hh;
    b_fi_l[idx] = __float2bfloat16_rn(v - __bfloat162float(hh));
}
// tail rows of q (agents without ego match) — depends only on d_remain
__global__ void build_q_tail_k(const float* __restrict__ xa) {
    int idx = blockIdx.x * blockDim.x + threadIdx.x;
    if (idx >= (LQ - LE) * CM) return;
    int row = idx >> 8;
    int c = idx & 255;
    float v = xa[d_remain[row] * CM + c];
    int g = LE * CM + idx;
    d_q[g] = v;
    __nv_bfloat16 hh = __float2bfloat16_rn(v);
    b_q_h[g] = hh;
    b_q_l[g] = __float2bfloat16_rn(v - __bfloat162float(hh));
}
__global__ void build_kv_k(const float* __restrict__ xe, const float* __restrict__ xa) {
    int idx = blockIdx.x * blockDim.x + threadIdx.x;
    if (idx >= LK * CM) return;
    int row = idx >> 8;
    float v = (row < LE) ? xe[idx] : xa[idx - LE * CM];
    __nv_bfloat16 hh = __float2bfloat16_rn(v);
    b_kv_h[idx] = hh;
    b_kv_l[idx] = __float2bfloat16_rn(v - __bfloat162float(hh));
}

// ---------------- output-mode codes ----------------
#define OUT_F32 0
#define OUT_SPLIT 1
#define OUT_BF16 2
#define OUT_KV 3
#define OUT_QSEL 4   // matched ? gemm : x_ego(Rm); writes Cf fp32 + Ch/Cl split

template <int OMODE, bool RELU, bool RESID>
static __device__ __forceinline__ void epi_store(
    float* acc4, int r0, int col, int N,
    const float* __restrict__ bias, const float* __restrict__ Rm,
    float* __restrict__ Cf, __nv_bfloat16* __restrict__ Ch, __nv_bfloat16* __restrict__ Cl) {
    float b0 = bias[col], b1 = bias[col + 1];
    float v0 = acc4[0] + b0, v1 = acc4[1] + b1;
    float v2 = acc4[2] + b0, v3 = acc4[3] + b1;
    if (RESID) {
        v0 += Rm[(size_t)r0 * N + col];       v1 += Rm[(size_t)r0 * N + col + 1];
        v2 += Rm[(size_t)(r0 + 8) * N + col]; v3 += Rm[(size_t)(r0 + 8) * N + col + 1];
    }
    if (RELU) {
        v0 = fmaxf(v0, 0.f); v1 = fmaxf(v1, 0.f);
        v2 = fmaxf(v2, 0.f); v3 = fmaxf(v3, 0.f);
    }
    size_t i0 = (size_t)r0 * N + col, i1 = (size_t)(r0 + 8) * N + col;
    if (OMODE == OUT_F32) {
        *(float2*)&Cf[i0] = make_float2(v0, v1);
        *(float2*)&Cf[i1] = make_float2(v2, v3);
    } else if (OMODE == OUT_BF16) {
        *(uint32_t*)&Ch[i0] = packbf(v0, v1);
        *(uint32_t*)&Ch[i1] = packbf(v2, v3);
    } else if (OMODE == OUT_SPLIT) {
        uint32_t ph, pl;
        split2(v0, v1, ph, pl);
        *(uint32_t*)&Ch[i0] = ph; *(uint32_t*)&Cl[i0] = pl;
        split2(v2, v3, ph, pl);
        *(uint32_t*)&Ch[i1] = ph; *(uint32_t*)&Cl[i1] = pl;
    } else if (OMODE == OUT_KV) {
        __nv_bfloat16* dst = (col < CM) ? Ch : Cl;
        int cc = col & (CM - 1);
        *(uint32_t*)&dst[(size_t)r0 * CM + cc] = packbf(v0, v1);
        *(uint32_t*)&dst[(size_t)(r0 + 8) * CM + cc] = packbf(v2, v3);
    } else {  // OUT_QSEL
        int m0 = d_matched[r0], m1 = d_matched[r0 + 8];
        if (!m0) { v0 = Rm[i0]; v1 = Rm[i0 + 1]; }
        if (!m1) { v2 = Rm[i1]; v3 = Rm[i1 + 1]; }
        *(float2*)&Cf[i0] = make_float2(v0, v1);
        *(float2*)&Cf[i1] = make_float2(v2, v3);
        uint32_t ph, pl;
        split2(v0, v1, ph, pl);
        *(uint32_t*)&Ch[i0] = ph; *(uint32_t*)&Cl[i0] = pl;
        split2(v2, v3, ph, pl);
        *(uint32_t*)&Ch[i1] = ph; *(uint32_t*)&Cl[i1] = pl;
    }
}

// ---------------- split-bf16 GEMM, BM=64, cp.async double-buffered ----------------
template <int OMODE, bool RELU, bool RESID>
__global__ void gemm_bs_k(const __nv_bfloat16* __restrict__ Ah, const __nv_bfloat16* __restrict__ Al,
                          const __nv_bfloat16* __restrict__ Wh, const __nv_bfloat16* __restrict__ Wl,
                          const float* __restrict__ bias, const float* __restrict__ Rm,
                          float* __restrict__ Cf, __nv_bfloat16* __restrict__ Ch,
                          __nv_bfloat16* __restrict__ Cl, int M, int N, int K) {
    __shared__ __nv_bfloat16 As[2][2][64][40];
    __shared__ __nv_bfloat16 Ws[2][2][64][40];
    int tid = threadIdx.x, lane = tid & 31, wid = tid >> 5;
    int bm = blockIdx.y << 6, bn = blockIdx.x << 6;
    int wm = (wid >> 1) << 4, wn = (wid & 1) << 5;

    float acc[4][4];
#pragma unroll
    for (int j = 0; j < 4; j++)
#pragma unroll
        for (int k = 0; k < 4; k++) acc[j][k] = 0.f;

    int lr = tid >> 2;
    int lc = (tid & 3) << 3;
    const __nv_bfloat16* gAh = Ah + (size_t)(bm + lr) * K + lc;
    const __nv_bfloat16* gAl = Al + (size_t)(bm + lr) * K + lc;
    const __nv_bfloat16* gWh = Wh + (size_t)(bn + lr) * K + lc;
    const __nv_bfloat16* gWl = Wl + (size_t)(bn + lr) * K + lc;

    int a_r = lane & 15, a_c = (lane >> 4) << 3;
    int b_r = (lane & 7) + ((lane >> 4) << 3), b_c = ((lane >> 3) & 1) << 3;
    int KT = K >> 5;

    {
        cpa16(&As[0][0][lr][lc], gAh);
        cpa16(&As[0][1][lr][lc], gAl);
        cpa16(&Ws[0][0][lr][lc], gWh);
        cpa16(&Ws[0][1][lr][lc], gWl);
        cpacommit();
    }

    for (int kt = 0; kt < KT; kt++) {
        int cur = kt & 1;
        if (kt + 1 < KT) {
            int k0 = (kt + 1) << 5;
            int nx = cur ^ 1;
            cpa16(&As[nx][0][lr][lc], gAh + k0);
            cpa16(&As[nx][1][lr][lc], gAl + k0);
            cpa16(&Ws[nx][0][lr][lc], gWh + k0);
            cpa16(&Ws[nx][1][lr][lc], gWl + k0);
            cpacommit();
            cpawait<1>();
        } else {
            cpawait<0>();
        }
        __syncthreads();
#pragma unroll
        for (int ks = 0; ks < 2; ks++) {
            uint32_t ah[4], al[4], bh[4][2], bl[4][2];
            ldm4(ah, &As[cur][0][wm + a_r][(ks << 4) + a_c]);
            ldm4(al, &As[cur][1][wm + a_r][(ks << 4) + a_c]);
#pragma unroll
            for (int np = 0; np < 2; np++) {
                uint32_t t4[4];
                ldm4(t4, &Ws[cur][0][wn + (np << 4) + b_r][(ks << 4) + b_c]);
                bh[np * 2][0] = t4[0]; bh[np * 2][1] = t4[1];
                bh[np * 2 + 1][0] = t4[2]; bh[np * 2 + 1][1] = t4[3];
                ldm4(t4, &Ws[cur][1][wn + (np << 4) + b_r][(ks << 4) + b_c]);
                bl[np * 2][0] = t4[0]; bl[np * 2][1] = t4[1];
                bl[np * 2 + 1][0] = t4[2]; bl[np * 2 + 1][1] = t4[3];
            }
#pragma unroll
            for (int nt = 0; nt < 4; nt++) {
                mma_bf16(acc[nt], ah, bh[nt]);
                mma_bf16(acc[nt], ah, bl[nt]);
                mma_bf16(acc[nt], al, bh[nt]);
            }
        }
        __syncthreads();
    }

    int g = lane >> 2, qd = lane & 3;
    int r0 = bm + wm + g;
#pragma unroll
    for (int nt = 0; nt < 4; nt++) {
        int col = bn + wn + (nt << 3) + (qd << 1);
        epi_store<OMODE, RELU, RESID>(acc[nt], r0, col, N, bias, Rm, Cf, Ch, Cl);
    }
}

// ---------------- flash attention, 64 q/block, 128 threads, cp.async kv pipeline ----------------
__global__ void attn_mma_k(const __nv_bfloat16* __restrict__ Qb, const __nv_bfloat16* __restrict__ Kb,
                           const __nv_bfloat16* __restrict__ Vb,
                           __nv_bfloat16* __restrict__ Oh, __nv_bfloat16* __restrict__ Ol) {
    __shared__ __nv_bfloat16 Qs[64][40];
    __shared__ __nv_bfloat16 Ks[2][64][40];
    __shared__ __nv_bfloat16 Vs[2][64][40];
    int tid = threadIdx.x, lane = tid & 31, wid = tid >> 5;
    int h = blockIdx.y, q0 = blockIdx.x << 6;
    int hc = h << 5;

    int ldr = tid >> 1, ldc = (tid & 1) << 4;

    {
        const __nv_bfloat16* pk = Kb + (size_t)ldr * CM + hc + ldc;
        const __nv_bfloat16* pv = Vb + (size_t)ldr * CM + hc + ldc;
        cpa16(&Ks[0][ldr][ldc], pk);
        cpa16(&Ks[0][ldr][ldc + 8], pk + 8);
        cpa16(&Vs[0][ldr][ldc], pv);
        cpa16(&Vs[0][ldr][ldc + 8], pv + 8);
        cpacommit();
    }
    {
        const uint4* p = (const uint4*)(Qb + (size_t)(q0 + ldr) * CM + hc + ldc);
        *(uint4*)&Qs[ldr][ldc] = p[0];
        *(uint4*)&Qs[ldr][ldc + 8] = p[1];
    }
    __syncthreads();

    int a_r = lane & 15, a_c = (lane >> 4) << 3;
    uint32_t qf[2][4];
    ldm4(qf[0], &Qs[(wid << 4) + a_r][a_c]);
    ldm4(qf[1], &Qs[(wid << 4) + a_r][16 + a_c]);

    float o[4][4];
#pragma unroll
    for (int i = 0; i < 4; i++)
#pragma unroll
        for (int j = 0; j < 4; j++) o[i][j] = 0.f;
    float m0 = -1e30f, m1 = -1e30f, l0 = 0.f, l1 = 0.f;

    int b_r = (lane & 7) + ((lane >> 4) << 3), b_c = ((lane >> 3) & 1) << 3;
    int NT = LK / 64;

    for (int t = 0; t < NT; t++) {
        int cur = t & 1;
        if (t + 1 < NT) {
            int nx = cur ^ 1;
            const __nv_bfloat16* pk = Kb + (size_t)((t + 1) * 64 + ldr) * CM + hc + ldc;
            const __nv_bfloat16* pv = Vb + (size_t)((t + 1) * 64 + ldr) * CM + hc + ldc;
            cpa16(&Ks[nx][ldr][ldc], pk);
            cpa16(&Ks[nx][ldr][ldc + 8], pk + 8);
            cpa16(&Vs[nx][ldr][ldc], pv);
            cpa16(&Vs[nx][ldr][ldc + 8], pv + 8);
            cpacommit();
            cpawait<1>();
        } else {
            cpawait<0>();
        }
        __syncthreads();

        float s[8][4];
#pragma unroll
        for (int j = 0; j < 8; j++)
#pragma unroll
            for (int c = 0; c < 4; c++) s[j][c] = 0.f;
#pragma unroll
        for (int ks = 0; ks < 2; ks++) {
#pragma unroll
            for (int jp = 0; jp < 4; jp++) {
                uint32_t t4[4];
                ldm4(t4, &Ks[cur][(jp << 4) + b_r][(ks << 4) + b_c]);
                uint32_t bb0[2] = {t4[0], t4[1]};
                uint32_t bb1[2] = {t4[2], t4[3]};
                mma_bf16(s[jp * 2], qf[ks], bb0);
                mma_bf16(s[jp * 2 + 1], qf[ks], bb1);
            }
        }
#pragma unroll
        for (int j = 0; j < 8; j++) {
            s[j][0] *= SCALE; s[j][1] *= SCALE; s[j][2] *= SCALE; s[j][3] *= SCALE;
        }

        float rmax0 = -1e30f, rmax1 = -1e30f;
#pragma unroll
        for (int j = 0; j < 8; j++) {
            rmax0 = fmaxf(rmax0, fmaxf(s[j][0], s[j][1]));
            rmax1 = fmaxf(rmax1, fmaxf(s[j][2], s[j][3]));
        }
        rmax0 = fmaxf(rmax0, __shfl_xor_sync(0xffffffffu, rmax0, 1));
        rmax0 = fmaxf(rmax0, __shfl_xor_sync(0xffffffffu, rmax0, 2));
        rmax1 = fmaxf(rmax1, __shfl_xor_sync(0xffffffffu, rmax1, 1));
        rmax1 = fmaxf(rmax1, __shfl_xor_sync(0xffffffffu, rmax1, 2));

        float mn0 = fmaxf(m0, rmax0), mn1 = fmaxf(m1, rmax1);
        float c0 = __expf(m0 - mn0), c1 = __expf(m1 - mn1);
        float sum0 = 0.f, sum1 = 0.f;
        uint32_t pa[4][4];
#pragma unroll
        for (int jj = 0; jj < 4; jj++) {
            float p00 = __expf(s[2 * jj][0] - mn0),     p01 = __expf(s[2 * jj][1] - mn0);
            float p02 = __expf(s[2 * jj][2] - mn1),     p03 = __expf(s[2 * jj][3] - mn1);
            float p10 = __expf(s[2 * jj + 1][0] - mn0), p11 = __expf(s[2 * jj + 1][1] - mn0);
            float p12 = __expf(s[2 * jj + 1][2] - mn1), p13 = __expf(s[2 * jj + 1][3] - mn1);
            sum0 += p00 + p01 + p10 + p11;
            sum1 += p02 + p03 + p12 + p13;
            pa[jj][0] = packbf(p00, p01);
            pa[jj][1] = packbf(p02, p03);
            pa[jj][2] = packbf(p10, p11);
            pa[jj][3] = packbf(p12, p13);
        }
        sum0 += __shfl_xor_sync(0xffffffffu, sum0, 1);
        sum0 += __shfl_xor_sync(0xffffffffu, sum0, 2);
        sum1 += __shfl_xor_sync(0xffffffffu, sum1, 1);
        sum1 += __shfl_xor_sync(0xffffffffu, sum1, 2);
        l0 = l0 * c0 + sum0;
        l1 = l1 * c1 + sum1;
        m0 = mn0; m1 = mn1;
#pragma unroll
        for (int nt = 0; nt < 4; nt++) {
            o[nt][0] *= c0; o[nt][1] *= c0; o[nt][2] *= c1; o[nt][3] *= c1;
        }

#pragma unroll
        for (int jj = 0; jj < 4; jj++) {
            uint32_t t4[4];
            ldm4t(t4, &Vs[cur][(jj << 4) + (lane & 15)][(lane >> 4) << 3]);
            {
                uint32_t bb0[2] = {t4[0], t4[1]};
                uint32_t bb1[2] = {t4[2], t4[3]};
                mma_bf16(o[0], pa[jj], bb0);
                mma_bf16(o[1], pa[jj], bb1);
            }
            ldm4t(t4, &Vs[cur][(jj << 4) + (lane & 15)][16 + ((lane >> 4) << 3)]);
            {
                uint32_t bb0[2] = {t4[0], t4[1]};
                uint32_t bb1[2] = {t4[2], t4[3]};
                mma_bf16(o[2], pa[jj], bb0);
                mma_bf16(o[3], pa[jj], bb1);
            }
        }
        __syncthreads();
    }

    float inv0 = 1.f / l0, inv1 = 1.f / l1;
    int g = lane >> 2, qd = lane & 3;
    int row0 = q0 + (wid << 4) + g;
#pragma unroll
    for (int nt = 0; nt < 4; nt++) {
        int col = hc + (nt << 3) + (qd << 1);
        uint32_t ph, pl;
        split2(o[nt][0] * inv0, o[nt][1] * inv0, ph, pl);
        *(uint32_t*)&Oh[(size_t)row0 * CM + col] = ph;
        *(uint32_t*)&Ol[(size_t)row0 * CM + col] = pl;
        split2(o[nt][2] * inv1, o[nt][3] * inv1, ph, pl);
        *(uint32_t*)&Oh[(size_t)(row0 + 8) * CM + col] = ph;
        *(uint32_t*)&Ol[(size_t)(row0 + 8) * CM + col] = pl;
    }
}

// ---------------- LayerNorm ----------------
template <bool SPLIT>
__global__ void ln_k(const float* __restrict__ X, const float* __restrict__ g,
                     const float* __restrict__ b, float* __restrict__ Y,
                     __nv_bfloat16* __restrict__ Yh, __nv_bfloat16* __restrict__ Yl) {
    int row = blockIdx.x;
    int c = threadIdx.x;
    float v = X[row * CM + c];
    float s = v, s2 = v * v;
#pragma unroll
    for (int o = 16; o > 0; o >>= 1) {
        s += __shfl_xor_sync(0xffffffffu, s, o);
        s2 += __shfl_xor_sync(0xffffffffu, s2, o);
    }
    __shared__ float rs[8], rs2[8];
    int w = c >> 5, lane = c & 31;
    if (lane == 0) { rs[w] = s; rs2[w] = s2; }
    __syncthreads();
    float tot = 0.f, tot2 = 0.f;
#pragma unroll
    for (int i = 0; i < 8; i++) { tot += rs[i]; tot2 += rs2[i]; }
    float mean = tot * (1.f / 256.f);
    float var = tot2 * (1.f / 256.f) - mean * mean;
    float is = rsqrtf(var + 1e-5f);
    float y = (v - mean) * is * g[c] + b[c];
    Y[row * CM + c] = y;
    if (SPLIT) {
        __nv_bfloat16 hh = __float2bfloat16_rn(y);
        Yh[row * CM + c] = hh;
        Yl[row * CM + c] = __float2bfloat16_rn(y - __bfloat162float(hh));
    }
}

// ---------------- launcher ----------------
#define SYM(p, s) cudaGetSymbolAddress((void**)&p, s)

extern "C" void kernel_launch(void* const* d_in, const int* in_sizes, int n_in,
                              void* d_out, int out_size) {
    const float* x_ego  = (const float*)d_in[0];
    const float* x_agent = (const float*)d_in[1];
    const float* Wf1 = (const float*)d_in[2];
    const float* bf1 = (const float*)d_in[3];
    const float* Wf2 = (const float*)d_in[4];
    const float* bf2 = (const float*)d_in[5];
    const float* Wf3 = (const float*)d_in[6];
    const float* bf3 = (const float*)d_in[7];
    const float* Wqkv = (const float*)d_in[8];
    const float* bqkv = (const float*)d_in[9];
    const float* Wo = (const float*)d_in[10];
    const float* bo = (const float*)d_in[11];
    const float* W1 = (const float*)d_in[12];
    const float* b1 = (const float*)d_in[13];
    const float* W2 = (const float*)d_in[14];
    const float* b2 = (const float*)d_in[15];
    const float* g1 = (const float*)d_in[16];
    const float* be1 = (const float*)d_in[17];
    const float* g2 = (const float*)d_in[18];
    const float* be2 = (const float*)d_in[19];
    const int* pos_ego = (const int*)d_in[20];
    const int* pos_agent = (const int*)d_in[21];
    float* out = (float*)d_out;

    float *p_q, *p_res1, *p_yq, *p_res2;
    SYM(p_q, d_q); SYM(p_res1, d_res1);
    SYM(p_yq, d_yq); SYM(p_res2, d_res2);

    __nv_bfloat16 *fi_h, *fi_l, *h1_h, *h1_l, *h2_h, *h2_l, *q_h, *q_l, *kv_h, *kv_l;
    __nv_bfloat16 *Qb, *Kb, *Vb, *at_h, *at_l, *yq_h, *yq_l, *ff_h, *ff_l;
    __nv_bfloat16 *wf1_h, *wf1_l, *wf2_h, *wf2_l, *wf3_h, *wf3_l;
    __nv_bfloat16 *wqkv_h, *wqkv_l, *wo_h, *wo_l, *w1_h, *w1_l, *w2_h, *w2_l;
    SYM(fi_h, b_fi_h); SYM(fi_l, b_fi_l);
    SYM(h1_h, b_h1_h); SYM(h1_l, b_h1_l);
    SYM(h2_h, b_h2_h); SYM(h2_l, b_h2_l);
    SYM(q_h, b_q_h); SYM(q_l, b_q_l);
    SYM(kv_h, b_kv_h); SYM(kv_l, b_kv_l);
    SYM(Qb, b_Q); SYM(Kb, b_K); SYM(Vb, b_V);
    SYM(at_h, b_at_h); SYM(at_l, b_at_l);
    SYM(yq_h, b_yq_h); SYM(yq_l, b_yq_l);
    SYM(ff_h, b_ff_h); SYM(ff_l, b_ff_l);
    SYM(wf1_h, b_wf1_h); SYM(wf1_l, b_wf1_l);
    SYM(wf2_h, b_wf2_h); SYM(wf2_l, b_wf2_l);
    SYM(wf3_h, b_wf3_h); SYM(wf3_l, b_wf3_l);
    SYM(wqkv_h, b_wqkv_h); SYM(wqkv_l, b_wqkv_l);
    SYM(wo_h, b_wo_h); SYM(wo_l, b_wo_l);
    SYM(w1_h, b_w1_h); SYM(w1_l, b_w1_l);
    SYM(w2_h, b_w2_h); SYM(w2_l, b_w2_l);

    static cudaStream_t sA = nullptr, sB = nullptr;
    static cudaEvent_t ev0, ev1, ev2;
    if (!sA) {
        cudaStreamCreateWithFlags(&sA, cudaStreamNonBlocking);
        cudaStreamCreateWithFlags(&sB, cudaStreamNonBlocking);
        cudaEventCreateWithFlags(&ev0, cudaEventDisableTiming);
        cudaEventCreateWithFlags(&ev1, cudaEventDisableTiming);
        cudaEventCreateWithFlags(&ev2, cudaEventDisableTiming);
    }

    WS ws;
    ws.s[0] = Wf1;  ws.h[0] = wf1_h;  ws.l[0] = wf1_l;
    ws.s[1] = Wf2;  ws.h[1] = wf2_h;  ws.l[1] = wf2_l;
    ws.s[2] = Wf3;  ws.h[2] = wf3_h;  ws.l[2] = wf3_l;
    ws.s[3] = Wqkv; ws.h[3] = wqkv_h; ws.l[3] = wqkv_l;
    ws.s[4] = Wo;   ws.h[4] = wo_h;   ws.l[4] = wo_l;
    ws.s[5] = W1;   ws.h[5] = w1_h;   ws.l[5] = w1_l;
    ws.s[6] = W2;   ws.h[6] = w2_h;   ws.l[6] = w2_l;
    ws.off[0] = 0;       ws.off[1] = 131072;  ws.off[2] = 196608; ws.off[3] = 262144;
    ws.off[4] = 458752;  ws.off[5] = 524288;  ws.off[6] = 786432; ws.off[7] = 1048576;

    // fork point
    cudaEventRecord(ev0, 0);

    // branch A: weight splits
    cudaStreamWaitEvent(sA, ev0, 0);
    wsplit_k<<<4096, 256, 0, sA>>>(ws);
    cudaEventRecord(ev1, sA);

    // branch B: kv build + K/V projection
    cudaStreamWaitEvent(sB, ev0, 0);
    build_kv_k<<<(LK * CM) / 256, 256, 0, sB>>>(x_ego, x_agent);
    cudaStreamWaitEvent(sB, ev1, 0);
    gemm_bs_k<OUT_KV, false, false><<<dim3(2 * CM / 64, LK / 64), 256, 0, sB>>>(
        kv_h, kv_l, wqkv_h + CM * CM, wqkv_l + CM * CM, bqkv + CM, nullptr,
        nullptr, Kb, Vb, LK, 2 * CM, CM);
    cudaEventRecord(ev2, sB);

    // main branch: matching, fusion MLP (q assembled in f3 epilogue), Q proj
    match_all_k<<<1, 1024>>>(pos_ego, pos_agent);
    build_q_tail_k<<<((LQ - LE) * CM) / 256, 256>>>(x_agent);
    build_fusedin_k<<<(LE * 2 * CM) / 256, 256>>>(x_ego, x_agent);
    cudaStreamWaitEvent(0, ev1, 0);
    gemm_bs_k<OUT_SPLIT, true, false><<<dim3(CM / 64, LE / 64), 256>>>(
        fi_h, fi_l, wf1_h, wf1_l, bf1, nullptr, nullptr, h1_h, h1_l, LE, CM, 2 * CM);
    gemm_bs_k<OUT_SPLIT, true, false><<<dim3(CM / 64, LE / 64), 256>>>(
        h1_h, h1_l, wf2_h, wf2_l, bf2, nullptr, nullptr, h2_h, h2_l, LE, CM, CM);
    gemm_bs_k<OUT_QSEL, false, false><<<dim3(CM / 64, LE / 64), 256>>>(
        h2_h, h2_l, wf3_h, wf3_l, bf3, x_ego, p_q, q_h, q_l, LE, CM, CM);
    gemm_bs_k<OUT_BF16, false, false><<<dim3(CM / 64, LQ / 64), 256>>>(
        q_h, q_l, wqkv_h, wqkv_l, bqkv, nullptr, nullptr, Qb, nullptr, LQ, CM, CM);

    // join: attention needs K/V
    cudaStreamWaitEvent(0, ev2, 0);
    attn_mma_k<<<dim3(LQ / 64, HN), 128>>>(Qb, Kb, Vb, at_h, at_l);

    gemm_bs_k<OUT_F32, false, true><<<dim3(CM / 64, LQ / 64), 256>>>(
        at_h, at_l, wo_h, wo_l, bo, p_q, p_res1, nullptr, nullptr, LQ, CM, CM);
    ln_k<true><<<LQ, 256>>>(p_res1, g1, be1, p_yq, yq_h, yq_l);
    gemm_bs_k<OUT_SPLIT, true, false><<<dim3(DF / 64, LQ / 64), 256>>>(
        yq_h, yq_l, w1_h, w1_l, b1, nullptr, nullptr, ff_h, ff_l, LQ, DF, CM);
    gemm_bs_k<OUT_F32, false, true><<<dim3(CM / 64, LQ / 64), 256>>>(
        ff_h, ff_l, w2_h, w2_l, b2, p_yq, p_res2, nullptr, nullptr, LQ, CM, DF);
    ln_k<false><<<LQ, 256>>>(p_res2, g2, be2, out, nullptr, nullptr);
}

// round 12
// speedup vs baseline: 1.1239x; 1.0478x over previous
#include <cuda_runtime.h>
#include <cuda_bf16.h>
#include <cstdint>

// ---------------- problem constants ----------------
#define LE 2048
#define LA 2048
#define CM 256          // d_model
#define HN 8            // heads
#define DH 32           // head dim
#define DF 1024         // ffn dim
#define LQ 3072         // 2048 + 1024 remain
#define LK 4096         // 2048 + 2048
#define SCALE 0.17677669529663687f   // 1/sqrt(32)

#define HT_SIZE 4096
#define HT_MASK (HT_SIZE - 1)
#define HT_EMPTY 0xFFFFFFFFFFFFFFFFull

// ---------------- fp32 scratch ----------------
__device__ float d_q[LQ * CM];
__device__ float d_res1[LQ * CM];
__device__ float d_yq[LQ * CM];
__device__ float d_res2[LQ * CM];
__device__ int d_matched[LE];
__device__ int d_afe[LE];
__device__ int d_unmatched[LA];
__device__ int d_remain[LA];
__device__ unsigned long long d_ht[HT_SIZE];

// ---------------- bf16 scratch ----------------
__device__ __nv_bfloat16 b_fi_h[LE * 2 * CM], b_fi_l[LE * 2 * CM];
__device__ __nv_bfloat16 b_h1_h[LE * CM], b_h1_l[LE * CM];
__device__ __nv_bfloat16 b_h2_h[LE * CM], b_h2_l[LE * CM];
__device__ __nv_bfloat16 b_q_h[LQ * CM], b_q_l[LQ * CM];
__device__ __nv_bfloat16 b_kv_h[LK * CM], b_kv_l[LK * CM];
__device__ __nv_bfloat16 b_Q[LQ * CM];
__device__ __nv_bfloat16 b_K[LK * CM];
__device__ __nv_bfloat16 b_V[LK * CM];
__device__ __nv_bfloat16 b_at_h[LQ * CM], b_at_l[LQ * CM];
__device__ __nv_bfloat16 b_yq_h[LQ * CM], b_yq_l[LQ * CM];
__device__ __nv_bfloat16 b_ff_h[LQ * DF], b_ff_l[LQ * DF];
__device__ __nv_bfloat16 b_wf1_h[CM * 2 * CM], b_wf1_l[CM * 2 * CM];
__device__ __nv_bfloat16 b_wf2_h[CM * CM], b_wf2_l[CM * CM];
__device__ __nv_bfloat16 b_wf3_h[CM * CM], b_wf3_l[CM * CM];
__device__ __nv_bfloat16 b_wqkv_h[3 * CM * CM], b_wqkv_l[3 * CM * CM];
__device__ __nv_bfloat16 b_wo_h[CM * CM], b_wo_l[CM * CM];
__device__ __nv_bfloat16 b_w1_h[DF * CM], b_w1_l[DF * CM];
__device__ __nv_bfloat16 b_w2_h[CM * DF], b_w2_l[CM * DF];

// ---------------- helpers ----------------
static __device__ __forceinline__ uint32_t smem_u32(const void* p) {
    return (uint32_t)__cvta_generic_to_shared(p);
}
static __device__ __forceinline__ void ldm4(uint32_t* r, const void* p) {
    uint32_t a = smem_u32(p);
    asm volatile("ldmatrix.sync.aligned.m8n8.x4.shared.b16 {%0,%1,%2,%3}, [%4];\n"
                 : "=r"(r[0]), "=r"(r[1]), "=r"(r[2]), "=r"(r[3]) : "r"(a));
}
static __device__ __forceinline__ void ldm4t(uint32_t* r, const void* p) {
    uint32_t a = smem_u32(p);
    asm volatile("ldmatrix.sync.aligned.m8n8.x4.trans.shared.b16 {%0,%1,%2,%3}, [%4];\n"
                 : "=r"(r[0]), "=r"(r[1]), "=r"(r[2]), "=r"(r[3]) : "r"(a));
}
static __device__ __forceinline__ void mma_bf16(float* c, const uint32_t* a, const uint32_t* b) {
    asm volatile("mma.sync.aligned.m16n8k16.row.col.f32.bf16.bf16.f32 "
                 "{%0,%1,%2,%3}, {%4,%5,%6,%7}, {%8,%9}, {%0,%1,%2,%3};\n"
                 : "+f"(c[0]), "+f"(c[1]), "+f"(c[2]), "+f"(c[3])
                 : "r"(a[0]), "r"(a[1]), "r"(a[2]), "r"(a[3]), "r"(b[0]), "r"(b[1]));
}
static __device__ __forceinline__ uint32_t packbf(float lo, float hi) {
    uint32_t r;
    asm("cvt.rn.bf16x2.f32 %0, %1, %2;" : "=r"(r) : "f"(hi), "f"(lo));
    return r;
}
static __device__ __forceinline__ void split2(float v0, float v1, uint32_t& ph, uint32_t& pl) {
    __nv_bfloat16 h0 = __float2bfloat16_rn(v0), h1 = __float2bfloat16_rn(v1);
    float l0 = v0 - __bfloat162float(h0);
    float l1 = v1 - __bfloat162float(h1);
    ph = ((uint32_t)__bfloat16_as_ushort(h1) << 16) | (uint32_t)__bfloat16_as_ushort(h0);
    pl = packbf(l0, l1);
}
static __device__ __forceinline__ void cpa16(void* dst, const void* src) {
    uint32_t d = smem_u32(dst);
    asm volatile("cp.async.cg.shared.global [%0], [%1], 16;\n" :: "r"(d), "l"(src));
}
static __device__ __forceinline__ void cpacommit() {
    asm volatile("cp.async.commit_group;\n");
}
template <int N>
static __device__ __forceinline__ void cpawait() {
    asm volatile("cp.async.wait_group %0;\n" :: "n"(N));
}
static __device__ __forceinline__ uint32_t ht_hash(uint32_t k) {
    return (k * 2654435761u) & HT_MASK;
}

// ---------------- single-kernel matching + compaction (1 block, 1024 threads) ----------------
__global__ void match_all_k(const int* __restrict__ pe, const int* __restrict__ pa) {
    int t = threadIdx.x;
#pragma unroll
    for (int i = t; i < HT_SIZE; i += 1024) d_ht[i] = HT_EMPTY;
    __syncthreads();
#pragma unroll
    for (int j = t; j < LA; j += 1024) {
        d_unmatched[j] = 1;
        uint32_t key = (uint32_t)pa[j];
        unsigned long long entry = ((unsigned long long)key << 32) | (uint32_t)j;
        uint32_t h = ht_hash(key);
        while (true) {
            unsigned long long prev = atomicCAS(&d_ht[h], HT_EMPTY, entry);
            if (prev == HT_EMPTY) break;
            h = (h + 1) & HT_MASK;
        }
    }
    __syncthreads();
#pragma unroll
    for (int i = t; i < LE; i += 1024) {
        uint32_t key = (uint32_t)pe[i];
        uint32_t h = ht_hash(key);
        int m = 0, a = 0;
        while (true) {
            unsigned long long e = d_ht[h];
            if (e == HT_EMPTY) break;
            if ((uint32_t)(e >> 32) == key) { m = 1; a = (int)(uint32_t)e; break; }
            h = (h + 1) & HT_MASK;
        }
        d_matched[i] = m;
        d_afe[i] = a;
        if (m) d_unmatched[a] = 0;
    }
    __syncthreads();
    __shared__ int wsum[32];
    int f0 = d_unmatched[2 * t], f1 = d_unmatched[2 * t + 1];
    int s = f0 + f1;
    int lane = t & 31, w = t >> 5;
    int v = s;
#pragma unroll
    for (int o = 1; o < 32; o <<= 1) {
        int n = __shfl_up_sync(0xffffffffu, v, o);
        if (lane >= o) v += n;
    }
    if (lane == 31) wsum[w] = v;
    __syncthreads();
    if (w == 0) {
        int x = wsum[lane];
#pragma unroll
        for (int o = 1; o < 32; o <<= 1) {
            int n = __shfl_up_sync(0xffffffffu, x, o);
            if (lane >= o) x += n;
        }
        wsum[lane] = x;
    }
    __syncthreads();
    int base = (w > 0 ? wsum[w - 1] : 0) + (v - s);
    if (f0) d_remain[base] = 2 * t;
    if (f1) d_remain[base + f0] = 2 * t + 1;
}

// ---------------- one-shot weight split ----------------
struct WS {
    const float* s[7];
    __nv_bfloat16* h[7];
    __nv_bfloat16* l[7];
    int off[8];
};
__global__ void wsplit_k(WS ws) {
    int i = blockIdx.x * blockDim.x + threadIdx.x;
    int r = 0;
#pragma unroll
    for (int j = 1; j < 7; j++)
        if (i >= ws.off[j]) r = j;
    int loc = i - ws.off[r];
    float v = ws.s[r][loc];
    __nv_bfloat16 hh = __float2bfloat16_rn(v);
    ws.h[r][loc] = hh;
    ws.l[r][loc] = __float2bfloat16_rn(v - __bfloat162float(hh));
}

// ---------------- fused builds (fusedin + q tail in one kernel) ----------------
#define FI_N (LE * 2 * CM)
#define QT_N ((LQ - LE) * CM)
__global__ void build_fi_qt_k(const float* __restrict__ xe, const float* __restrict__ xa) {
    int idx = blockIdx.x * blockDim.x + threadIdx.x;
    if (idx < FI_N) {
        int row = idx >> 9;
        int c = idx & 511;
        float v = (c < CM) ? xe[row * CM + c] : xa[d_afe[row] * CM + (c - CM)];
        __nv_bfloat16 hh = __float2bfloat16_rn(v);
        b_fi_h[idx] = hh;
        b_fi_l[idx] = __float2bfloat16_rn(v - __bfloat162float(hh));
    } else if (idx < FI_N + QT_N) {
        int k = idx - FI_N;
        int row = k >> 8;
        int c = k & 255;
        float v = xa[d_remain[row] * CM + c];
        int g = LE * CM + k;
        d_q[g] = v;
        __nv_bfloat16 hh = __float2bfloat16_rn(v);
        b_q_h[g] = hh;
        b_q_l[g] = __float2bfloat16_rn(v - __bfloat162float(hh));
    }
}
__global__ void build_kv_k(const float* __restrict__ xe, const float* __restrict__ xa) {
    int idx = blockIdx.x * blockDim.x + threadIdx.x;
    if (idx >= LK * CM) return;
    int row = idx >> 8;
    float v = (row < LE) ? xe[idx] : xa[idx - LE * CM];
    __nv_bfloat16 hh = __float2bfloat16_rn(v);
    b_kv_h[idx] = hh;
    b_kv_l[idx] = __float2bfloat16_rn(v - __bfloat162float(hh));
}

// ---------------- output-mode codes ----------------
#define OUT_F32 0
#define OUT_SPLIT 1
#define OUT_BF16 2
#define OUT_KV 3
#define OUT_QSEL 4   // matched ? gemm : x_ego(Rm); writes Cf fp32 + Ch/Cl split

template <int OMODE, bool RELU, bool RESID>
static __device__ __forceinline__ void epi_store(
    float* acc4, int r0, int col, int N,
    const float* __restrict__ bias, const float* __restrict__ Rm,
    float* __restrict__ Cf, __nv_bfloat16* __restrict__ Ch, __nv_bfloat16* __restrict__ Cl) {
    float b0 = bias[col], b1 = bias[col + 1];
    float v0 = acc4[0] + b0, v1 = acc4[1] + b1;
    float v2 = acc4[2] + b0, v3 = acc4[3] + b1;
    if (RESID) {
        v0 += Rm[(size_t)r0 * N + col];       v1 += Rm[(size_t)r0 * N + col + 1];
        v2 += Rm[(size_t)(r0 + 8) * N + col]; v3 += Rm[(size_t)(r0 + 8) * N + col + 1];
    }
    if (RELU) {
        v0 = fmaxf(v0, 0.f); v1 = fmaxf(v1, 0.f);
        v2 = fmaxf(v2, 0.f); v3 = fmaxf(v3, 0.f);
    }
    size_t i0 = (size_t)r0 * N + col, i1 = (size_t)(r0 + 8) * N + col;
    if (OMODE == OUT_F32) {
        *(float2*)&Cf[i0] = make_float2(v0, v1);
        *(float2*)&Cf[i1] = make_float2(v2, v3);
    } else if (OMODE == OUT_BF16) {
        *(uint32_t*)&Ch[i0] = packbf(v0, v1);
        *(uint32_t*)&Ch[i1] = packbf(v2, v3);
    } else if (OMODE == OUT_SPLIT) {
        uint32_t ph, pl;
        split2(v0, v1, ph, pl);
        *(uint32_t*)&Ch[i0] = ph; *(uint32_t*)&Cl[i0] = pl;
        split2(v2, v3, ph, pl);
        *(uint32_t*)&Ch[i1] = ph; *(uint32_t*)&Cl[i1] = pl;
    } else if (OMODE == OUT_KV) {
        __nv_bfloat16* dst = (col < CM) ? Ch : Cl;
        int cc = col & (CM - 1);
        *(uint32_t*)&dst[(size_t)r0 * CM + cc] = packbf(v0, v1);
        *(uint32_t*)&dst[(size_t)(r0 + 8) * CM + cc] = packbf(v2, v3);
    } else {  // OUT_QSEL
        int m0 = d_matched[r0], m1 = d_matched[r0 + 8];
        if (!m0) { v0 = Rm[i0]; v1 = Rm[i0 + 1]; }
        if (!m1) { v2 = Rm[i1]; v3 = Rm[i1 + 1]; }
        *(float2*)&Cf[i0] = make_float2(v0, v1);
        *(float2*)&Cf[i1] = make_float2(v2, v3);
        uint32_t ph, pl;
        split2(v0, v1, ph, pl);
        *(uint32_t*)&Ch[i0] = ph; *(uint32_t*)&Cl[i0] = pl;
        split2(v2, v3, ph, pl);
        *(uint32_t*)&Ch[i1] = ph; *(uint32_t*)&Cl[i1] = pl;
    }
}

// ---------------- split-bf16 GEMM, BM=64, cp.async double-buffered ----------------
// SP3=true: 3-pass hi/lo split. SP3=false: single-pass bf16 (Al/Wl unused).
template <int OMODE, bool RELU, bool RESID, bool SP3>
__global__ void gemm_bs_k(const __nv_bfloat16* __restrict__ Ah, const __nv_bfloat16* __restrict__ Al,
                          const __nv_bfloat16* __restrict__ Wh, const __nv_bfloat16* __restrict__ Wl,
                          const float* __restrict__ bias, const float* __restrict__ Rm,
                          float* __restrict__ Cf, __nv_bfloat16* __restrict__ Ch,
                          __nv_bfloat16* __restrict__ Cl, int M, int N, int K) {
    __shared__ __nv_bfloat16 As[2][2][64][40];
    __shared__ __nv_bfloat16 Ws[2][2][64][40];
    int tid = threadIdx.x, lane = tid & 31, wid = tid >> 5;
    int bm = blockIdx.y << 6, bn = blockIdx.x << 6;
    int wm = (wid >> 1) << 4, wn = (wid & 1) << 5;

    float acc[4][4];
#pragma unroll
    for (int j = 0; j < 4; j++)
#pragma unroll
        for (int k = 0; k < 4; k++) acc[j][k] = 0.f;

    int lr = tid >> 2;
    int lc = (tid & 3) << 3;
    const __nv_bfloat16* gAh = Ah + (size_t)(bm + lr) * K + lc;
    const __nv_bfloat16* gAl = Al + (size_t)(bm + lr) * K + lc;
    const __nv_bfloat16* gWh = Wh + (size_t)(bn + lr) * K + lc;
    const __nv_bfloat16* gWl = Wl + (size_t)(bn + lr) * K + lc;

    int a_r = lane & 15, a_c = (lane >> 4) << 3;
    int b_r = (lane & 7) + ((lane >> 4) << 3), b_c = ((lane >> 3) & 1) << 3;
    int KT = K >> 5;

    {
        cpa16(&As[0][0][lr][lc], gAh);
        cpa16(&Ws[0][0][lr][lc], gWh);
        if (SP3) {
            cpa16(&As[0][1][lr][lc], gAl);
            cpa16(&Ws[0][1][lr][lc], gWl);
        }
        cpacommit();
    }

    for (int kt = 0; kt < KT; kt++) {
        int cur = kt & 1;
        if (kt + 1 < KT) {
            int k0 = (kt + 1) << 5;
            int nx = cur ^ 1;
            cpa16(&As[nx][0][lr][lc], gAh + k0);
            cpa16(&Ws[nx][0][lr][lc], gWh + k0);
            if (SP3) {
                cpa16(&As[nx][1][lr][lc], gAl + k0);
                cpa16(&Ws[nx][1][lr][lc], gWl + k0);
            }
            cpacommit();
            cpawait<1>();
        } else {
            cpawait<0>();
        }
        __syncthreads();
#pragma unroll
        for (int ks = 0; ks < 2; ks++) {
            uint32_t ah[4], al[4], bh[4][2], bl[4][2];
            ldm4(ah, &As[cur][0][wm + a_r][(ks << 4) + a_c]);
            if (SP3) ldm4(al, &As[cur][1][wm + a_r][(ks << 4) + a_c]);
#pragma unroll
            for (int np = 0; np < 2; np++) {
                uint32_t t4[4];
                ldm4(t4, &Ws[cur][0][wn + (np << 4) + b_r][(ks << 4) + b_c]);
                bh[np * 2][0] = t4[0]; bh[np * 2][1] = t4[1];
                bh[np * 2 + 1][0] = t4[2]; bh[np * 2 + 1][1] = t4[3];
                if (SP3) {
                    ldm4(t4, &Ws[cur][1][wn + (np << 4) + b_r][(ks << 4) + b_c]);
                    bl[np * 2][0] = t4[0]; bl[np * 2][1] = t4[1];
                    bl[np * 2 + 1][0] = t4[2]; bl[np * 2 + 1][1] = t4[3];
                }
            }
#pragma unroll
            for (int nt = 0; nt < 4; nt++) {
                mma_bf16(acc[nt], ah, bh[nt]);
                if (SP3) {
                    mma_bf16(acc[nt], ah, bl[nt]);
                    mma_bf16(acc[nt], al, bh[nt]);
                }
            }
        }
        __syncthreads();
    }

    int g = lane >> 2, qd = lane & 3;
    int r0 = bm + wm + g;
#pragma unroll
    for (int nt = 0; nt < 4; nt++) {
        int col = bn + wn + (nt << 3) + (qd << 1);
        epi_store<OMODE, RELU, RESID>(acc[nt], r0, col, N, bias, Rm, Cf, Ch, Cl);
    }
}

// ---------------- flash attention, 64 q/block, 128 threads, cp.async kv pipeline ----------------
__global__ void attn_mma_k(const __nv_bfloat16* __restrict__ Qb, const __nv_bfloat16* __restrict__ Kb,
                           const __nv_bfloat16* __restrict__ Vb,
                           __nv_bfloat16* __restrict__ Oh, __nv_bfloat16* __restrict__ Ol) {
    __shared__ __nv_bfloat16 Qs[64][40];
    __shared__ __nv_bfloat16 Ks[2][64][40];
    __shared__ __nv_bfloat16 Vs[2][64][40];
    int tid = threadIdx.x, lane = tid & 31, wid = tid >> 5;
    int h = blockIdx.y, q0 = blockIdx.x << 6;
    int hc = h << 5;

    int ldr = tid >> 1, ldc = (tid & 1) << 4;

    {
        const __nv_bfloat16* pk = Kb + (size_t)ldr * CM + hc + ldc;
        const __nv_bfloat16* pv = Vb + (size_t)ldr * CM + hc + ldc;
        cpa16(&Ks[0][ldr][ldc], pk);
        cpa16(&Ks[0][ldr][ldc + 8], pk + 8);
        cpa16(&Vs[0][ldr][ldc], pv);
        cpa16(&Vs[0][ldr][ldc + 8], pv + 8);
        cpacommit();
    }
    {
        const uint4* p = (const uint4*)(Qb + (size_t)(q0 + ldr) * CM + hc + ldc);
        *(uint4*)&Qs[ldr][ldc] = p[0];
        *(uint4*)&Qs[ldr][ldc + 8] = p[1];
    }
    __syncthreads();

    int a_r = lane & 15, a_c = (lane >> 4) << 3;
    uint32_t qf[2][4];
    ldm4(qf[0], &Qs[(wid << 4) + a_r][a_c]);
    ldm4(qf[1], &Qs[(wid << 4) + a_r][16 + a_c]);

    float o[4][4];
#pragma unroll
    for (int i = 0; i < 4; i++)
#pragma unroll
        for (int j = 0; j < 4; j++) o[i][j] = 0.f;
    float m0 = -1e30f, m1 = -1e30f, l0 = 0.f, l1 = 0.f;

    int b_r = (lane & 7) + ((lane >> 4) << 3), b_c = ((lane >> 3) & 1) << 3;
    int NT = LK / 64;

    for (int t = 0; t < NT; t++) {
        int cur = t & 1;
        if (t + 1 < NT) {
            int nx = cur ^ 1;
            const __nv_bfloat16* pk = Kb + (size_t)((t + 1) * 64 + ldr) * CM + hc + ldc;
            const __nv_bfloat16* pv = Vb + (size_t)((t + 1) * 64 + ldr) * CM + hc + ldc;
            cpa16(&Ks[nx][ldr][ldc], pk);
            cpa16(&Ks[nx][ldr][ldc + 8], pk + 8);
            cpa16(&Vs[nx][ldr][ldc], pv);
            cpa16(&Vs[nx][ldr][ldc + 8], pv + 8);
            cpacommit();
            cpawait<1>();
        } else {
            cpawait<0>();
        }
        __syncthreads();

        float s[8][4];
#pragma unroll
        for (int j = 0; j < 8; j++)
#pragma unroll
            for (int c = 0; c < 4; c++) s[j][c] = 0.f;
#pragma unroll
        for (int ks = 0; ks < 2; ks++) {
#pragma unroll
            for (int jp = 0; jp < 4; jp++) {
                uint32_t t4[4];
                ldm4(t4, &Ks[cur][(jp << 4) + b_r][(ks << 4) + b_c]);
                uint32_t bb0[2] = {t4[0], t4[1]};
                uint32_t bb1[2] = {t4[2], t4[3]};
                mma_bf16(s[jp * 2], qf[ks], bb0);
                mma_bf16(s[jp * 2 + 1], qf[ks], bb1);
            }
        }
#pragma unroll
        for (int j = 0; j < 8; j++) {
            s[j][0] *= SCALE; s[j][1] *= SCALE; s[j][2] *= SCALE; s[j][3] *= SCALE;
        }

        float rmax0 = -1e30f, rmax1 = -1e30f;
#pragma unroll
        for (int j = 0; j < 8; j++) {
            rmax0 = fmaxf(rmax0, fmaxf(s[j][0], s[j][1]));
            rmax1 = fmaxf(rmax1, fmaxf(s[j][2], s[j][3]));
        }
        rmax0 = fmaxf(rmax0, __shfl_xor_sync(0xffffffffu, rmax0, 1));
        rmax0 = fmaxf(rmax0, __shfl_xor_sync(0xffffffffu, rmax0, 2));
        rmax1 = fmaxf(rmax1, __shfl_xor_sync(0xffffffffu, rmax1, 1));
        rmax1 = fmaxf(rmax1, __shfl_xor_sync(0xffffffffu, rmax1, 2));

        float mn0 = fmaxf(m0, rmax0), mn1 = fmaxf(m1, rmax1);
        float c0 = __expf(m0 - mn0), c1 = __expf(m1 - mn1);
        float sum0 = 0.f, sum1 = 0.f;
        uint32_t pa[4][4];
#pragma unroll
        for (int jj = 0; jj < 4; jj++) {
            float p00 = __expf(s[2 * jj][0] - mn0),     p01 = __expf(s[2 * jj][1] - mn0);
            float p02 = __expf(s[2 * jj][2] - mn1),     p03 = __expf(s[2 * jj][3] - mn1);
            float p10 = __expf(s[2 * jj + 1][0] - mn0), p11 = __expf(s[2 * jj + 1][1] - mn0);
            float p12 = __expf(s[2 * jj + 1][2] - mn1), p13 = __expf(s[2 * jj + 1][3] - mn1);
            sum0 += p00 + p01 + p10 + p11;
            sum1 += p02 + p03 + p12 + p13;
            pa[jj][0] = packbf(p00, p01);
            pa[jj][1] = packbf(p02, p03);
            pa[jj][2] = packbf(p10, p11);
            pa[jj][3] = packbf(p12, p13);
        }
        sum0 += __shfl_xor_sync(0xffffffffu, sum0, 1);
        sum0 += __shfl_xor_sync(0xffffffffu, sum0, 2);
        sum1 += __shfl_xor_sync(0xffffffffu, sum1, 1);
        sum1 += __shfl_xor_sync(0xffffffffu, sum1, 2);
        l0 = l0 * c0 + sum0;
        l1 = l1 * c1 + sum1;
        m0 = mn0; m1 = mn1;
#pragma unroll
        for (int nt = 0; nt < 4; nt++) {
            o[nt][0] *= c0; o[nt][1] *= c0; o[nt][2] *= c1; o[nt][3] *= c1;
        }

#pragma unroll
        for (int jj = 0; jj < 4; jj++) {
            uint32_t t4[4];
            ldm4t(t4, &Vs[cur][(jj << 4) + (lane & 15)][(lane >> 4) << 3]);
            {
                uint32_t bb0[2] = {t4[0], t4[1]};
                uint32_t bb1[2] = {t4[2], t4[3]};
                mma_bf16(o[0], pa[jj], bb0);
                mma_bf16(o[1], pa[jj], bb1);
            }
            ldm4t(t4, &Vs[cur][(jj << 4) + (lane & 15)][16 + ((lane >> 4) << 3)]);
            {
                uint32_t bb0[2] = {t4[0], t4[1]};
                uint32_t bb1[2] = {t4[2], t4[3]};
                mma_bf16(o[2], pa[jj], bb0);
                mma_bf16(o[3], pa[jj], bb1);
            }
        }
        __syncthreads();
    }

    float inv0 = 1.f / l0, inv1 = 1.f / l1;
    int g = lane >> 2, qd = lane & 3;
    int row0 = q0 + (wid << 4) + g;
#pragma unroll
    for (int nt = 0; nt < 4; nt++) {
        int col = hc + (nt << 3) + (qd << 1);
        uint32_t ph, pl;
        split2(o[nt][0] * inv0, o[nt][1] * inv0, ph, pl);
        *(uint32_t*)&Oh[(size_t)row0 * CM + col] = ph;
        *(uint32_t*)&Ol[(size_t)row0 * CM + col] = pl;
        split2(o[nt][2] * inv1, o[nt][3] * inv1, ph, pl);
        *(uint32_t*)&Oh[(size_t)(row0 + 8) * CM + col] = ph;
        *(uint32_t*)&Ol[(size_t)(row0 + 8) * CM + col] = pl;
    }
}

// ---------------- LayerNorm ----------------
template <bool SPLIT>
__global__ void ln_k(const float* __restrict__ X, const float* __restrict__ g,
                     const float* __restrict__ b, float* __restrict__ Y,
                     __nv_bfloat16* __restrict__ Yh, __nv_bfloat16* __restrict__ Yl) {
    int row = blockIdx.x;
    int c = threadIdx.x;
    float v = X[row * CM + c];
    float s = v, s2 = v * v;
#pragma unroll
    for (int o = 16; o > 0; o >>= 1) {
        s += __shfl_xor_sync(0xffffffffu, s, o);
        s2 += __shfl_xor_sync(0xffffffffu, s2, o);
    }
    __shared__ float rs[8], rs2[8];
    int w = c >> 5, lane = c & 31;
    if (lane == 0) { rs[w] = s; rs2[w] = s2; }
    __syncthreads();
    float tot = 0.f, tot2 = 0.f;
#pragma unroll
    for (int i = 0; i < 8; i++) { tot += rs[i]; tot2 += rs2[i]; }
    float mean = tot * (1.f / 256.f);
    float var = tot2 * (1.f / 256.f) - mean * mean;
    float is = rsqrtf(var + 1e-5f);
    float y = (v - mean) * is * g[c] + b[c];
    Y[row * CM + c] = y;
    if (SPLIT) {
        __nv_bfloat16 hh = __float2bfloat16_rn(y);
        Yh[row * CM + c] = hh;
        Yl[row * CM + c] = __float2bfloat16_rn(y - __bfloat162float(hh));
    }
}

// ---------------- launcher ----------------
#define SYM(p, s) cudaGetSymbolAddress((void**)&p, s)

extern "C" void kernel_launch(void* const* d_in, const int* in_sizes, int n_in,
                              void* d_out, int out_size) {
    const float* x_ego  = (const float*)d_in[0];
    const float* x_agent = (const float*)d_in[1];
    const float* Wf1 = (const float*)d_in[2];
    const float* bf1 = (const float*)d_in[3];
    const float* Wf2 = (const float*)d_in[4];
    const float* bf2 = (const float*)d_in[5];
    const float* Wf3 = (const float*)d_in[6];
    const float* bf3 = (const float*)d_in[7];
    const float* Wqkv = (const float*)d_in[8];
    const float* bqkv = (const float*)d_in[9];
    const float* Wo = (const float*)d_in[10];
    const float* bo = (const float*)d_in[11];
    const float* W1 = (const float*)d_in[12];
    const float* b1 = (const float*)d_in[13];
    const float* W2 = (const float*)d_in[14];
    const float* b2 = (const float*)d_in[15];
    const float* g1 = (const float*)d_in[16];
    const float* be1 = (const float*)d_in[17];
    const float* g2 = (const float*)d_in[18];
    const float* be2 = (const float*)d_in[19];
    const int* pos_ego = (const int*)d_in[20];
    const int* pos_agent = (const int*)d_in[21];
    float* out = (float*)d_out;

    float *p_q, *p_res1, *p_yq, *p_res2;
    SYM(p_q, d_q); SYM(p_res1, d_res1);
    SYM(p_yq, d_yq); SYM(p_res2, d_res2);

    __nv_bfloat16 *fi_h, *fi_l, *h1_h, *h1_l, *h2_h, *h2_l, *q_h, *q_l, *kv_h, *kv_l;
    __nv_bfloat16 *Qb, *Kb, *Vb, *at_h, *at_l, *yq_h, *yq_l, *ff_h, *ff_l;
    __nv_bfloat16 *wf1_h, *wf1_l, *wf2_h, *wf2_l, *wf3_h, *wf3_l;
    __nv_bfloat16 *wqkv_h, *wqkv_l, *wo_h, *wo_l, *w1_h, *w1_l, *w2_h, *w2_l;
    SYM(fi_h, b_fi_h); SYM(fi_l, b_fi_l);
    SYM(h1_h, b_h1_h); SYM(h1_l, b_h1_l);
    SYM(h2_h, b_h2_h); SYM(h2_l, b_h2_l);
    SYM(q_h, b_q_h); SYM(q_l, b_q_l);
    SYM(kv_h, b_kv_h); SYM(kv_l, b_kv_l);
    SYM(Qb, b_Q); SYM(Kb, b_K); SYM(Vb, b_V);
    SYM(at_h, b_at_h); SYM(at_l, b_at_l);
    SYM(yq_h, b_yq_h); SYM(yq_l, b_yq_l);
    SYM(ff_h, b_ff_h); SYM(ff_l, b_ff_l);
    SYM(wf1_h, b_wf1_h); SYM(wf1_l, b_wf1_l);
    SYM(wf2_h, b_wf2_h); SYM(wf2_l, b_wf2_l);
    SYM(wf3_h, b_wf3_h); SYM(wf3_l, b_wf3_l);
    SYM(wqkv_h, b_wqkv_h); SYM(wqkv_l, b_wqkv_l);
    SYM(wo_h, b_wo_h); SYM(wo_l, b_wo_l);
    SYM(w1_h, b_w1_h); SYM(w1_l, b_w1_l);
    SYM(w2_h, b_w2_h); SYM(w2_l, b_w2_l);

    static cudaStream_t sA = nullptr, sB = nullptr;
    static cudaEvent_t ev0, ev1, ev2;
    if (!sA) {
        cudaStreamCreateWithFlags(&sA, cudaStreamNonBlocking);
        cudaStreamCreateWithFlags(&sB, cudaStreamNonBlocking);
        cudaEventCreateWithFlags(&ev0, cudaEventDisableTiming);
        cudaEventCreateWithFlags(&ev1, cudaEventDisableTiming);
        cudaEventCreateWithFlags(&ev2, cudaEventDisableTiming);
    }

    WS ws;
    ws.s[0] = Wf1;  ws.h[0] = wf1_h;  ws.l[0] = wf1_l;
    ws.s[1] = Wf2;  ws.h[1] = wf2_h;  ws.l[1] = wf2_l;
    ws.s[2] = Wf3;  ws.h[2] = wf3_h;  ws.l[2] = wf3_l;
    ws.s[3] = Wqkv; ws.h[3] = wqkv_h; ws.l[3] = wqkv_l;
    ws.s[4] = Wo;   ws.h[4] = wo_h;   ws.l[4] = wo_l;
    ws.s[5] = W1;   ws.h[5] = w1_h;   ws.l[5] = w1_l;
    ws.s[6] = W2;   ws.h[6] = w2_h;   ws.l[6] = w2_l;
    ws.off[0] = 0;       ws.off[1] = 131072;  ws.off[2] = 196608; ws.off[3] = 262144;
    ws.off[4] = 458752;  ws.off[5] = 524288;  ws.off[6] = 786432; ws.off[7] = 1048576;

    // fork point
    cudaEventRecord(ev0, 0);

    // branch A: weight splits
    cudaStreamWaitEvent(sA, ev0, 0);
    wsplit_k<<<4096, 256, 0, sA>>>(ws);
    cudaEventRecord(ev1, sA);

    // branch B: kv build + K/V projection (single-pass bf16)
    cudaStreamWaitEvent(sB, ev0, 0);
    build_kv_k<<<(LK * CM) / 256, 256, 0, sB>>>(x_ego, x_agent);
    cudaStreamWaitEvent(sB, ev1, 0);
    gemm_bs_k<OUT_KV, false, false, false><<<dim3(2 * CM / 64, LK / 64), 256, 0, sB>>>(
        kv_h, kv_l, wqkv_h + CM * CM, wqkv_l + CM * CM, bqkv + CM, nullptr,
        nullptr, Kb, Vb, LK, 2 * CM, CM);
    cudaEventRecord(ev2, sB);

    // main branch: matching, fused builds, fusion MLP (q in f3 epilogue), Q proj
    match_all_k<<<1, 1024>>>(pos_ego, pos_agent);
    build_fi_qt_k<<<(FI_N + QT_N) / 256, 256>>>(x_ego, x_agent);
    cudaStreamWaitEvent(0, ev1, 0);
    gemm_bs_k<OUT_SPLIT, true, false, true><<<dim3(CM / 64, LE / 64), 256>>>(
        fi_h, fi_l, wf1_h, wf1_l, bf1, nullptr, nullptr, h1_h, h1_l, LE, CM, 2 * CM);
    gemm_bs_k<OUT_SPLIT, true, false, true><<<dim3(CM / 64, LE / 64), 256>>>(
        h1_h, h1_l, wf2_h, wf2_l, bf2, nullptr, nullptr, h2_h, h2_l, LE, CM, CM);
    gemm_bs_k<OUT_QSEL, false, false, true><<<dim3(CM / 64, LE / 64), 256>>>(
        h2_h, h2_l, wf3_h, wf3_l, bf3, x_ego, p_q, q_h, q_l, LE, CM, CM);
    gemm_bs_k<OUT_BF16, false, false, false><<<dim3(CM / 64, LQ / 64), 256>>>(
        q_h, q_l, wqkv_h, wqkv_l, bqkv, nullptr, nullptr, Qb, nullptr, LQ, CM, CM);

    // join: attention needs K/V
    cudaStreamWaitEvent(0, ev2, 0);
    attn_mma_k<<<dim3(LQ / 64, HN), 128>>>(Qb, Kb, Vb, at_h, at_l);

    gemm_bs_k<OUT_F32, false, true, true><<<dim3(CM / 64, LQ / 64), 256>>>(
        at_h, at_l, wo_h, wo_l, bo, p_q, p_res1, nullptr, nullptr, LQ, CM, CM);
    ln_k<true><<<LQ, 256>>>(p_res1, g1, be1, p_yq, yq_h, yq_l);
    gemm_bs_k<OUT_SPLIT, true, false, true><<<dim3(DF / 64, LQ / 64), 256>>>(
        yq_h, yq_l, w1_h, w1_l, b1, nullptr, nullptr, ff_h, ff_l, LQ, DF, CM);
    gemm_bs_k<OUT_F32, false, true, true><<<dim3(CM / 64, LQ / 64), 256>>>(
        ff_h, ff_l, w2_h, w2_l, b2, p_yq, p_res2, nullptr, nullptr, LQ, CM, DF);
    ln_k<false><<<LQ, 256>>>(p_res2, g2, be2, out, nullptr, nullptr);
}

// round 16
// speedup vs baseline: 1.1344x; 1.0093x over previous
#include <cuda_runtime.h>
#include <cuda_bf16.h>
#include <cstdint>

// ---------------- problem constants ----------------
#define LE 2048
#define LA 2048
#define CM 256          // d_model
#define HN 8            // heads
#define DH 32           // head dim
#define DF 1024         // ffn dim
#define LQ 3072         // 2048 + 1024 remain
#define LK 4096         // 2048 + 2048
#define SCALE 0.17677669529663687f   // 1/sqrt(32)

#define HT_SIZE 4096
#define HT_MASK (HT_SIZE - 1)
#define HT_EMPTY 0xFFFFFFFFFFFFFFFFull

// ---------------- fp32 scratch ----------------
__device__ float d_q[LQ * CM];
__device__ float d_res1[LQ * CM];
__device__ float d_yq[LQ * CM];
__device__ float d_res2[LQ * CM];
__device__ int d_matched[LE];
__device__ int d_afe[LE];
__device__ int d_unmatched[LA];
__device__ int d_remain[LA];
__device__ int d_mrows[LE];     // compact list of matched ego rows
__device__ int d_mrank[LE];     // ego row -> compact rank (valid where matched)
__device__ int d_nm;            // number of matched ego rows
__device__ unsigned long long d_ht[HT_SIZE];

// ---------------- bf16 scratch ----------------
__device__ __nv_bfloat16 b_fi_h[LE * 2 * CM], b_fi_l[LE * 2 * CM];
__device__ __nv_bfloat16 b_h1_h[LE * CM], b_h1_l[LE * CM];
__device__ __nv_bfloat16 b_h2_h[LE * CM], b_h2_l[LE * CM];
__device__ __nv_bfloat16 b_q_h[LQ * CM], b_q_l[LQ * CM];
__device__ __nv_bfloat16 b_kv_h[LK * CM], b_kv_l[LK * CM];
__device__ __nv_bfloat16 b_Q[LQ * CM];
__device__ __nv_bfloat16 b_K[LK * CM];
__device__ __nv_bfloat16 b_V[LK * CM];
__device__ __nv_bfloat16 b_at_h[LQ * CM], b_at_l[LQ * CM];
__device__ __nv_bfloat16 b_yq_h[LQ * CM], b_yq_l[LQ * CM];
__device__ __nv_bfloat16 b_ff_h[LQ * DF], b_ff_l[LQ * DF];
__device__ __nv_bfloat16 b_wf1_h[CM * 2 * CM], b_wf1_l[CM * 2 * CM];
__device__ __nv_bfloat16 b_wf2_h[CM * CM], b_wf2_l[CM * CM];
__device__ __nv_bfloat16 b_wf3_h[CM * CM], b_wf3_l[CM * CM];
__device__ __nv_bfloat16 b_wqkv_h[3 * CM * CM], b_wqkv_l[3 * CM * CM];
__device__ __nv_bfloat16 b_wo_h[CM * CM], b_wo_l[CM * CM];
__device__ __nv_bfloat16 b_w1_h[DF * CM], b_w1_l[DF * CM];
__device__ __nv_bfloat16 b_w2_h[CM * DF], b_w2_l[CM * DF];

// ---------------- helpers ----------------
static __device__ __forceinline__ uint32_t smem_u32(const void* p) {
    return (uint32_t)__cvta_generic_to_shared(p);
}
static __device__ __forceinline__ void ldm4(uint32_t* r, const void* p) {
    uint32_t a = smem_u32(p);
    asm volatile("ldmatrix.sync.aligned.m8n8.x4.shared.b16 {%0,%1,%2,%3}, [%4];\n"
                 : "=r"(r[0]), "=r"(r[1]), "=r"(r[2]), "=r"(r[3]) : "r"(a));
}
static __device__ __forceinline__ void ldm4t(uint32_t* r, const void* p) {
    uint32_t a = smem_u32(p);
    asm volatile("ldmatrix.sync.aligned.m8n8.x4.trans.shared.b16 {%0,%1,%2,%3}, [%4];\n"
                 : "=r"(r[0]), "=r"(r[1]), "=r"(r[2]), "=r"(r[3]) : "r"(a));
}
static __device__ __forceinline__ void mma_bf16(float* c, const uint32_t* a, const uint32_t* b) {
    asm volatile("mma.sync.aligned.m16n8k16.row.col.f32.bf16.bf16.f32 "
                 "{%0,%1,%2,%3}, {%4,%5,%6,%7}, {%8,%9}, {%0,%1,%2,%3};\n"
                 : "+f"(c[0]), "+f"(c[1]), "+f"(c[2]), "+f"(c[3])
                 : "r"(a[0]), "r"(a[1]), "r"(a[2]), "r"(a[3]), "r"(b[0]), "r"(b[1]));
}
static __device__ __forceinline__ uint32_t packbf(float lo, float hi) {
    uint32_t r;
    asm("cvt.rn.bf16x2.f32 %0, %1, %2;" : "=r"(r) : "f"(hi), "f"(lo));
    return r;
}
static __device__ __forceinline__ void split2(float v0, float v1, uint32_t& ph, uint32_t& pl) {
    __nv_bfloat16 h0 = __float2bfloat16_rn(v0), h1 = __float2bfloat16_rn(v1);
    float l0 = v0 - __bfloat162float(h0);
    float l1 = v1 - __bfloat162float(h1);
    ph = ((uint32_t)__bfloat16_as_ushort(h1) << 16) | (uint32_t)__bfloat16_as_ushort(h0);
    pl = packbf(l0, l1);
}
static __device__ __forceinline__ void cpa16(void* dst, const void* src) {
    uint32_t d = smem_u32(dst);
    asm volatile("cp.async.cg.shared.global [%0], [%1], 16;\n" :: "r"(d), "l"(src));
}
static __device__ __forceinline__ void cpacommit() {
    asm volatile("cp.async.commit_group;\n");
}
template <int N>
static __device__ __forceinline__ void cpawait() {
    asm volatile("cp.async.wait_group %0;\n" :: "n"(N));
}
static __device__ __forceinline__ uint32_t ht_hash(uint32_t k) {
    return (k * 2654435761u) & HT_MASK;
}

// ---------------- single-kernel matching + compactions (1 block, 1024 threads) ----------------
__global__ void match_all_k(const int* __restrict__ pe, const int* __restrict__ pa) {
    int t = threadIdx.x;
    int lane = t & 31, w = t >> 5;
    __shared__ int wsum[32];
#pragma unroll
    for (int i = t; i < HT_SIZE; i += 1024) d_ht[i] = HT_EMPTY;
    __syncthreads();
#pragma unroll
    for (int j = t; j < LA; j += 1024) {
        d_unmatched[j] = 1;
        uint32_t key = (uint32_t)pa[j];
        unsigned long long entry = ((unsigned long long)key << 32) | (uint32_t)j;
        uint32_t h = ht_hash(key);
        while (true) {
            unsigned long long prev = atomicCAS(&d_ht[h], HT_EMPTY, entry);
            if (prev == HT_EMPTY) break;
            h = (h + 1) & HT_MASK;
        }
    }
    __syncthreads();
#pragma unroll
    for (int i = t; i < LE; i += 1024) {
        uint32_t key = (uint32_t)pe[i];
        uint32_t h = ht_hash(key);
        int m = 0, a = 0;
        while (true) {
            unsigned long long e = d_ht[h];
            if (e == HT_EMPTY) break;
            if ((uint32_t)(e >> 32) == key) { m = 1; a = (int)(uint32_t)e; break; }
            h = (h + 1) & HT_MASK;
        }
        d_matched[i] = m;
        d_afe[i] = a;
        if (m) d_unmatched[a] = 0;
    }
    __syncthreads();

    // ---- scan 1: compact matched ego rows ----
    {
        int f0 = d_matched[2 * t], f1 = d_matched[2 * t + 1];
        int s = f0 + f1;
        int v = s;
#pragma unroll
        for (int o = 1; o < 32; o <<= 1) {
            int n = __shfl_up_sync(0xffffffffu, v, o);
            if (lane >= o) v += n;
        }
        if (lane == 31) wsum[w] = v;
        __syncthreads();
        if (w == 0) {
            int x = wsum[lane];
#pragma unroll
            for (int o = 1; o < 32; o <<= 1) {
                int n = __shfl_up_sync(0xffffffffu, x, o);
                if (lane >= o) x += n;
            }
            wsum[lane] = x;
        }
        __syncthreads();
        int base = (w > 0 ? wsum[w - 1] : 0) + (v - s);
        if (f0) { d_mrows[base] = 2 * t;          d_mrank[2 * t] = base; }
        if (f1) { d_mrows[base + f0] = 2 * t + 1; d_mrank[2 * t + 1] = base + f0; }
        if (t == 1023) d_nm = (w > 0 ? wsum[w - 1] : 0) + v;
        __syncthreads();
    }

    // ---- scan 2: compact unmatched agent rows ----
    {
        int f0 = d_unmatched[2 * t], f1 = d_unmatched[2 * t + 1];
        int s = f0 + f1;
        int v = s;
#pragma unroll
        for (int o = 1; o < 32; o <<= 1) {
            int n = __shfl_up_sync(0xffffffffu, v, o);
            if (lane >= o) v += n;
        }
        if (lane == 31) wsum[w] = v;
        __syncthreads();
        if (w == 0) {
            int x = wsum[lane];
#pragma unroll
            for (int o = 1; o < 32; o <<= 1) {
                int n = __shfl_up_sync(0xffffffffu, x, o);
                if (lane >= o) x += n;
            }
            wsum[lane] = x;
        }
        __syncthreads();
        int base = (w > 0 ? wsum[w - 1] : 0) + (v - s);
        if (f0) d_remain[base] = 2 * t;
        if (f1) d_remain[base + f0] = 2 * t + 1;
    }
}

// ---------------- one-shot weight split ----------------
struct WS {
    const float* s[7];
    __nv_bfloat16* h[7];
    __nv_bfloat16* l[7];
    int off[8];
};
__global__ void wsplit_k(WS ws) {
    int i = blockIdx.x * blockDim.x + threadIdx.x;
    int r = 0;
#pragma unroll
    for (int j = 1; j < 7; j++)
        if (i >= ws.off[j]) r = j;
    int loc = i - ws.off[r];
    float v = ws.s[r][loc];
    __nv_bfloat16 hh = __float2bfloat16_rn(v);
    ws.h[r][loc] = hh;
    ws.l[r][loc] = __float2bfloat16_rn(v - __bfloat162float(hh));
}

// ---------------- fused builds: compact fusedin, unmatched-ego q, q tail ----------------
#define FI_N (LE * 2 * CM)
#define QT_N ((LQ - LE) * CM)
__global__ void build_fi_qt_k(const float* __restrict__ xe, const float* __restrict__ xa) {
    int idx = blockIdx.x * blockDim.x + threadIdx.x;
    if (idx < FI_N) {
        int row = idx >> 9;
        int c = idx & 511;
        if (d_matched[row]) {
            // compacted fusion-MLP input row
            float v = (c < CM) ? xe[row * CM + c] : xa[d_afe[row] * CM + (c - CM)];
            int cr = d_mrank[row];
            int g = (cr << 9) + c;
            __nv_bfloat16 hh = __float2bfloat16_rn(v);
            b_fi_h[g] = hh;
            b_fi_l[g] = __float2bfloat16_rn(v - __bfloat162float(hh));
        } else if (c < CM) {
            // unmatched ego row: q = x_ego directly
            float v = xe[row * CM + c];
            int g = row * CM + c;
            d_q[g] = v;
            __nv_bfloat16 hh = __float2bfloat16_rn(v);
            b_q_h[g] = hh;
            b_q_l[g] = __float2bfloat16_rn(v - __bfloat162float(hh));
        }
    } else if (idx < FI_N + QT_N) {
        int k = idx - FI_N;
        int row = k >> 8;
        int c = k & 255;
        float v = xa[d_remain[row] * CM + c];
        int g = LE * CM + k;
        d_q[g] = v;
        __nv_bfloat16 hh = __float2bfloat16_rn(v);
        b_q_h[g] = hh;
        b_q_l[g] = __float2bfloat16_rn(v - __bfloat162float(hh));
    }
}
__global__ void build_kv_k(const float* __restrict__ xe, const float* __restrict__ xa) {
    int idx = blockIdx.x * blockDim.x + threadIdx.x;
    if (idx >= LK * CM) return;
    int row = idx >> 8;
    float v = (row < LE) ? xe[idx] : xa[idx - LE * CM];
    __nv_bfloat16 hh = __float2bfloat16_rn(v);
    b_kv_h[idx] = hh;
    b_kv_l[idx] = __float2bfloat16_rn(v - __bfloat162float(hh));
}

// ---------------- output-mode codes ----------------
#define OUT_F32 0
#define OUT_SPLIT 1
#define OUT_BF16 2
#define OUT_KV 3
#define OUT_QSCAT 5  // scatter gemm+bias to q rows via d_mrows (fp32 + split)

template <int OMODE, bool RELU, bool RESID>
static __device__ __forceinline__ void epi_store(
    float* acc4, int r0, int col, int N,
    const float* __restrict__ bias, const float* __restrict__ Rm,
    float* __restrict__ Cf, __nv_bfloat16* __restrict__ Ch, __nv_bfloat16* __restrict__ Cl) {
    float b0 = bias[col], b1 = bias[col + 1];
    float v0 = acc4[0] + b0, v1 = acc4[1] + b1;
    float v2 = acc4[2] + b0, v3 = acc4[3] + b1;
    if (RESID) {
        v0 += Rm[(size_t)r0 * N + col];       v1 += Rm[(size_t)r0 * N + col + 1];
        v2 += Rm[(size_t)(r0 + 8) * N + col]; v3 += Rm[(size_t)(r0 + 8) * N + col + 1];
    }
    if (RELU) {
        v0 = fmaxf(v0, 0.f); v1 = fmaxf(v1, 0.f);
        v2 = fmaxf(v2, 0.f); v3 = fmaxf(v3, 0.f);
    }
    size_t i0 = (size_t)r0 * N + col, i1 = (size_t)(r0 + 8) * N + col;
    if (OMODE == OUT_F32) {
        *(float2*)&Cf[i0] = make_float2(v0, v1);
        *(float2*)&Cf[i1] = make_float2(v2, v3);
    } else if (OMODE == OUT_BF16) {
        *(uint32_t*)&Ch[i0] = packbf(v0, v1);
        *(uint32_t*)&Ch[i1] = packbf(v2, v3);
    } else if (OMODE == OUT_SPLIT) {
        uint32_t ph, pl;
        split2(v0, v1, ph, pl);
        *(uint32_t*)&Ch[i0] = ph; *(uint32_t*)&Cl[i0] = pl;
        split2(v2, v3, ph, pl);
        *(uint32_t*)&Ch[i1] = ph; *(uint32_t*)&Cl[i1] = pl;
    } else if (OMODE == OUT_KV) {
        __nv_bfloat16* dst = (col < CM) ? Ch : Cl;
        int cc = col & (CM - 1);
        *(uint32_t*)&dst[(size_t)r0 * CM + cc] = packbf(v0, v1);
        *(uint32_t*)&dst[(size_t)(r0 + 8) * CM + cc] = packbf(v2, v3);
    } else {  // OUT_QSCAT
        int nm = d_nm;
        if (r0 < nm) {
            size_t o0 = (size_t)d_mrows[r0] * N + col;
            *(float2*)&Cf[o0] = make_float2(v0, v1);
            uint32_t ph, pl;
            split2(v0, v1, ph, pl);
            *(uint32_t*)&Ch[o0] = ph; *(uint32_t*)&Cl[o0] = pl;
        }
        if (r0 + 8 < nm) {
            size_t o1 = (size_t)d_mrows[r0 + 8] * N + col;
            *(float2*)&Cf[o1] = make_float2(v2, v3);
            uint32_t ph, pl;
            split2(v2, v3, ph, pl);
            *(uint32_t*)&Ch[o1] = ph; *(uint32_t*)&Cl[o1] = pl;
        }
    }
}

// ---------------- split-bf16 GEMM, BM=64, cp.async double-buffered ----------------
// SP3: 3-pass hi/lo split vs single-pass bf16. MLIMIT: early-exit blocks with bm >= d_nm.
template <int OMODE, bool RELU, bool RESID, bool SP3, bool MLIMIT>
__global__ void gemm_bs_k(const __nv_bfloat16* __restrict__ Ah, const __nv_bfloat16* __restrict__ Al,
                          const __nv_bfloat16* __restrict__ Wh, const __nv_bfloat16* __restrict__ Wl,
                          const float* __restrict__ bias, const float* __restrict__ Rm,
                          float* __restrict__ Cf, __nv_bfloat16* __restrict__ Ch,
                          __nv_bfloat16* __restrict__ Cl, int M, int N, int K) {
    int bm = blockIdx.y << 6, bn = blockIdx.x << 6;
    if (MLIMIT && bm >= d_nm) return;
    __shared__ __nv_bfloat16 As[2][2][64][40];
    __shared__ __nv_bfloat16 Ws[2][2][64][40];
    int tid = threadIdx.x, lane = tid & 31, wid = tid >> 5;
    int wm = (wid >> 1) << 4, wn = (wid & 1) << 5;

    float acc[4][4];
#pragma unroll
    for (int j = 0; j < 4; j++)
#pragma unroll
        for (int k = 0; k < 4; k++) acc[j][k] = 0.f;

    int lr = tid >> 2;
    int lc = (tid & 3) << 3;
    const __nv_bfloat16* gAh = Ah + (size_t)(bm + lr) * K + lc;
    const __nv_bfloat16* gAl = Al + (size_t)(bm + lr) * K + lc;
    const __nv_bfloat16* gWh = Wh + (size_t)(bn + lr) * K + lc;
    const __nv_bfloat16* gWl = Wl + (size_t)(bn + lr) * K + lc;

    int a_r = lane & 15, a_c = (lane >> 4) << 3;
    int b_r = (lane & 7) + ((lane >> 4) << 3), b_c = ((lane >> 3) & 1) << 3;
    int KT = K >> 5;

    {
        cpa16(&As[0][0][lr][lc], gAh);
        cpa16(&Ws[0][0][lr][lc], gWh);
        if (SP3) {
            cpa16(&As[0][1][lr][lc], gAl);
            cpa16(&Ws[0][1][lr][lc], gWl);
        }
        cpacommit();
    }

    for (int kt = 0; kt < KT; kt++) {
        int cur = kt & 1;
        if (kt + 1 < KT) {
            int k0 = (kt + 1) << 5;
            int nx = cur ^ 1;
            cpa16(&As[nx][0][lr][lc], gAh + k0);
            cpa16(&Ws[nx][0][lr][lc], gWh + k0);
            if (SP3) {
                cpa16(&As[nx][1][lr][lc], gAl + k0);
                cpa16(&Ws[nx][1][lr][lc], gWl + k0);
            }
            cpacommit();
            cpawait<1>();
        } else {
            cpawait<0>();
        }
        __syncthreads();
#pragma unroll
        for (int ks = 0; ks < 2; ks++) {
            uint32_t ah[4], al[4], bh[4][2], bl[4][2];
            ldm4(ah, &As[cur][0][wm + a_r][(ks << 4) + a_c]);
            if (SP3) ldm4(al, &As[cur][1][wm + a_r][(ks << 4) + a_c]);
#pragma unroll
            for (int np = 0; np < 2; np++) {
                uint32_t t4[4];
                ldm4(t4, &Ws[cur][0][wn + (np << 4) + b_r][(ks << 4) + b_c]);
                bh[np * 2][0] = t4[0]; bh[np * 2][1] = t4[1];
                bh[np * 2 + 1][0] = t4[2]; bh[np * 2 + 1][1] = t4[3];
                if (SP3) {
                    ldm4(t4, &Ws[cur][1][wn + (np << 4) + b_r][(ks << 4) + b_c]);
                    bl[np * 2][0] = t4[0]; bl[np * 2][1] = t4[1];
                    bl[np * 2 + 1][0] = t4[2]; bl[np * 2 + 1][1] = t4[3];
                }
            }
#pragma unroll
            for (int nt = 0; nt < 4; nt++) {
                mma_bf16(acc[nt], ah, bh[nt]);
                if (SP3) {
                    mma_bf16(acc[nt], ah, bl[nt]);
                    mma_bf16(acc[nt], al, bh[nt]);
                }
            }
        }
        __syncthreads();
    }

    int g = lane >> 2, qd = lane & 3;
    int r0 = bm + wm + g;
#pragma unroll
    for (int nt = 0; nt < 4; nt++) {
        int col = bn + wn + (nt << 3) + (qd << 1);
        epi_store<OMODE, RELU, RESID>(acc[nt], r0, col, N, bias, Rm, Cf, Ch, Cl);
    }
}

// ---------------- flash attention, 64 q/block, 128 threads, cp.async kv pipeline ----------------
__global__ void attn_mma_k(const __nv_bfloat16* __restrict__ Qb, const __nv_bfloat16* __restrict__ Kb,
                           const __nv_bfloat16* __restrict__ Vb,
                           __nv_bfloat16* __restrict__ Oh, __nv_bfloat16* __restrict__ Ol) {
    __shared__ __nv_bfloat16 Qs[64][40];
    __shared__ __nv_bfloat16 Ks[2][64][40];
    __shared__ __nv_bfloat16 Vs[2][64][40];
    int tid = threadIdx.x, lane = tid & 31, wid = tid >> 5;
    int h = blockIdx.y, q0 = blockIdx.x << 6;
    int hc = h << 5;

    int ldr = tid >> 1, ldc = (tid & 1) << 4;

    {
        const __nv_bfloat16* pk = Kb + (size_t)ldr * CM + hc + ldc;
        const __nv_bfloat16* pv = Vb + (size_t)ldr * CM + hc + ldc;
        cpa16(&Ks[0][ldr][ldc], pk);
        cpa16(&Ks[0][ldr][ldc + 8], pk + 8);
        cpa16(&Vs[0][ldr][ldc], pv);
        cpa16(&Vs[0][ldr][ldc + 8], pv + 8);
        cpacommit();
    }
    {
        const uint4* p = (const uint4*)(Qb + (size_t)(q0 + ldr) * CM + hc + ldc);
        *(uint4*)&Qs[ldr][ldc] = p[0];
        *(uint4*)&Qs[ldr][ldc + 8] = p[1];
    }
    __syncthreads();

    int a_r = lane & 15, a_c = (lane >> 4) << 3;
    uint32_t qf[2][4];
    ldm4(qf[0], &Qs[(wid << 4) + a_r][a_c]);
    ldm4(qf[1], &Qs[(wid << 4) + a_r][16 + a_c]);

    float o[4][4];
#pragma unroll
    for (int i = 0; i < 4; i++)
#pragma unroll
        for (int j = 0; j < 4; j++) o[i][j] = 0.f;
    float m0 = -1e30f, m1 = -1e30f, l0 = 0.f, l1 = 0.f;

    int b_r = (lane & 7) + ((lane >> 4) << 3), b_c = ((lane >> 3) & 1) << 3;
    int NT = LK / 64;

    for (int t = 0; t < NT; t++) {
        int cur = t & 1;
        if (t + 1 < NT) {
            int nx = cur ^ 1;
            const __nv_bfloat16* pk = Kb + (size_t)((t + 1) * 64 + ldr) * CM + hc + ldc;
            const __nv_bfloat16* pv = Vb + (size_t)((t + 1) * 64 + ldr) * CM + hc + ldc;
            cpa16(&Ks[nx][ldr][ldc], pk);
            cpa16(&Ks[nx][ldr][ldc + 8], pk + 8);
            cpa16(&Vs[nx][ldr][ldc], pv);
            cpa16(&Vs[nx][ldr][ldc + 8], pv + 8);
            cpacommit();
            cpawait<1>();
        } else {
            cpawait<0>();
        }
        __syncthreads();

        float s[8][4];
#pragma unroll
        for (int j = 0; j < 8; j++)
#pragma unroll
            for (int c = 0; c < 4; c++) s[j][c] = 0.f;
#pragma unroll
        for (int ks = 0; ks < 2; ks++) {
#pragma unroll
            for (int jp = 0; jp < 4; jp++) {
                uint32_t t4[4];
                ldm4(t4, &Ks[cur][(jp << 4) + b_r][(ks << 4) + b_c]);
                uint32_t bb0[2] = {t4[0], t4[1]};
                uint32_t bb1[2] = {t4[2], t4[3]};
                mma_bf16(s[jp * 2], qf[ks], bb0);
                mma_bf16(s[jp * 2 + 1], qf[ks], bb1);
            }
        }
#pragma unroll
        for (int j = 0; j < 8; j++) {
            s[j][0] *= SCALE; s[j][1] *= SCALE; s[j][2] *= SCALE; s[j][3] *= SCALE;
        }

        float rmax0 = -1e30f, rmax1 = -1e30f;
#pragma unroll
        for (int j = 0; j < 8; j++) {
            rmax0 = fmaxf(rmax0, fmaxf(s[j][0], s[j][1]));
            rmax1 = fmaxf(rmax1, fmaxf(s[j][2], s[j][3]));
        }
        rmax0 = fmaxf(rmax0, __shfl_xor_sync(0xffffffffu, rmax0, 1));
        rmax0 = fmaxf(rmax0, __shfl_xor_sync(0xffffffffu, rmax0, 2));
        rmax1 = fmaxf(rmax1, __shfl_xor_sync(0xffffffffu, rmax1, 1));
        rmax1 = fmaxf(rmax1, __shfl_xor_sync(0xffffffffu, rmax1, 2));

        float mn0 = fmaxf(m0, rmax0), mn1 = fmaxf(m1, rmax1);
        float c0 = __expf(m0 - mn0), c1 = __expf(m1 - mn1);
        float sum0 = 0.f, sum1 = 0.f;
        uint32_t pa[4][4];
#pragma unroll
        for (int jj = 0; jj < 4; jj++) {
            float p00 = __expf(s[2 * jj][0] - mn0),     p01 = __expf(s[2 * jj][1] - mn0);
            float p02 = __expf(s[2 * jj][2] - mn1),     p03 = __expf(s[2 * jj][3] - mn1);
            float p10 = __expf(s[2 * jj + 1][0] - mn0), p11 = __expf(s[2 * jj + 1][1] - mn0);
            float p12 = __expf(s[2 * jj + 1][2] - mn1), p13 = __expf(s[2 * jj + 1][3] - mn1);
            sum0 += p00 + p01 + p10 + p11;
            sum1 += p02 + p03 + p12 + p13;
            pa[jj][0] = packbf(p00, p01);
            pa[jj][1] = packbf(p02, p03);
            pa[jj][2] = packbf(p10, p11);
            pa[jj][3] = packbf(p12, p13);
        }
        sum0 += __shfl_xor_sync(0xffffffffu, sum0, 1);
        sum0 += __shfl_xor_sync(0xffffffffu, sum0, 2);
        sum1 += __shfl_xor_sync(0xffffffffu, sum1, 1);
        sum1 += __shfl_xor_sync(0xffffffffu, sum1, 2);
        l0 = l0 * c0 + sum0;
        l1 = l1 * c1 + sum1;
        m0 = mn0; m1 = mn1;
#pragma unroll
        for (int nt = 0; nt < 4; nt++) {
            o[nt][0] *= c0; o[nt][1] *= c0; o[nt][2] *= c1; o[nt][3] *= c1;
        }

#pragma unroll
        for (int jj = 0; jj < 4; jj++) {
            uint32_t t4[4];
            ldm4t(t4, &Vs[cur][(jj << 4) + (lane & 15)][(lane >> 4) << 3]);
            {
                uint32_t bb0[2] = {t4[0], t4[1]};
                uint32_t bb1[2] = {t4[2], t4[3]};
                mma_bf16(o[0], pa[jj], bb0);
                mma_bf16(o[1], pa[jj], bb1);
            }
            ldm4t(t4, &Vs[cur][(jj << 4) + (lane & 15)][16 + ((lane >> 4) << 3)]);
            {
                uint32_t bb0[2] = {t4[0], t4[1]};
                uint32_t bb1[2] = {t4[2], t4[3]};
                mma_bf16(o[2], pa[jj], bb0);
                mma_bf16(o[3], pa[jj], bb1);
            }
        }
        __syncthreads();
    }

    float inv0 = 1.f / l0, inv1 = 1.f / l1;
    int g = lane >> 2, qd = lane & 3;
    int row0 = q0 + (wid << 4) + g;
#pragma unroll
    for (int nt = 0; nt < 4; nt++) {
        int col = hc + (nt << 3) + (qd << 1);
        uint32_t ph, pl;
        split2(o[nt][0] * inv0, o[nt][1] * inv0, ph, pl);
        *(uint32_t*)&Oh[(size_t)row0 * CM + col] = ph;
        *(uint32_t*)&Ol[(size_t)row0 * CM + col] = pl;
        split2(o[nt][2] * inv1, o[nt][3] * inv1, ph, pl);
        *(uint32_t*)&Oh[(size_t)(row0 + 8) * CM + col] = ph;
        *(uint32_t*)&Ol[(size_t)(row0 + 8) * CM + col] = pl;
    }
}

// ---------------- LayerNorm ----------------
template <bool SPLIT>
__global__ void ln_k(const float* __restrict__ X, const float* __restrict__ g,
                     const float* __restrict__ b, float* __restrict__ Y,
                     __nv_bfloat16* __restrict__ Yh, __nv_bfloat16* __restrict__ Yl) {
    int row = blockIdx.x;
    int c = threadIdx.x;
    float v = X[row * CM + c];
    float s = v, s2 = v * v;
#pragma unroll
    for (int o = 16; o > 0; o >>= 1) {
        s += __shfl_xor_sync(0xffffffffu, s, o);
        s2 += __shfl_xor_sync(0xffffffffu, s2, o);
    }
    __shared__ float rs[8], rs2[8];
    int w = c >> 5, lane = c & 31;
    if (lane == 0) { rs[w] = s; rs2[w] = s2; }
    __syncthreads();
    float tot = 0.f, tot2 = 0.f;
#pragma unroll
    for (int i = 0; i < 8; i++) { tot += rs[i]; tot2 += rs2[i]; }
    float mean = tot * (1.f / 256.f);
    float var = tot2 * (1.f / 256.f) - mean * mean;
    float is = rsqrtf(var + 1e-5f);
    float y = (v - mean) * is * g[c] + b[c];
    Y[row * CM + c] = y;
    if (SPLIT) {
        __nv_bfloat16 hh = __float2bfloat16_rn(y);
        Yh[row * CM + c] = hh;
        Yl[row * CM + c] = __float2bfloat16_rn(y - __bfloat162float(hh));
    }
}

// ---------------- launcher ----------------
#define SYM(p, s) cudaGetSymbolAddress((void**)&p, s)

extern "C" void kernel_launch(void* const* d_in, const int* in_sizes, int n_in,
                              void* d_out, int out_size) {
    const float* x_ego  = (const float*)d_in[0];
    const float* x_agent = (const float*)d_in[1];
    const float* Wf1 = (const float*)d_in[2];
    const float* bf1 = (const float*)d_in[3];
    const float* Wf2 = (const float*)d_in[4];
    const float* bf2 = (const float*)d_in[5];
    const float* Wf3 = (const float*)d_in[6];
    const float* bf3 = (const float*)d_in[7];
    const float* Wqkv = (const float*)d_in[8];
    const float* bqkv = (const float*)d_in[9];
    const float* Wo = (const float*)d_in[10];
    const float* bo = (const float*)d_in[11];
    const float* W1 = (const float*)d_in[12];
    const float* b1 = (const float*)d_in[13];
    const float* W2 = (const float*)d_in[14];
    const float* b2 = (const float*)d_in[15];
    const float* g1 = (const float*)d_in[16];
    const float* be1 = (const float*)d_in[17];
    const float* g2 = (const float*)d_in[18];
    const float* be2 = (const float*)d_in[19];
    const int* pos_ego = (const int*)d_in[20];
    const int* pos_agent = (const int*)d_in[21];
    float* out = (float*)d_out;

    float *p_q, *p_res1, *p_yq, *p_res2;
    SYM(p_q, d_q); SYM(p_res1, d_res1);
    SYM(p_yq, d_yq); SYM(p_res2, d_res2);

    __nv_bfloat16 *fi_h, *fi_l, *h1_h, *h1_l, *h2_h, *h2_l, *q_h, *q_l, *kv_h, *kv_l;
    __nv_bfloat16 *Qb, *Kb, *Vb, *at_h, *at_l, *yq_h, *yq_l, *ff_h, *ff_l;
    __nv_bfloat16 *wf1_h, *wf1_l, *wf2_h, *wf2_l, *wf3_h, *wf3_l;
    __nv_bfloat16 *wqkv_h, *wqkv_l, *wo_h, *wo_l, *w1_h, *w1_l, *w2_h, *w2_l;
    SYM(fi_h, b_fi_h); SYM(fi_l, b_fi_l);
    SYM(h1_h, b_h1_h); SYM(h1_l, b_h1_l);
    SYM(h2_h, b_h2_h); SYM(h2_l, b_h2_l);
    SYM(q_h, b_q_h); SYM(q_l, b_q_l);
    SYM(kv_h, b_kv_h); SYM(kv_l, b_kv_l);
    SYM(Qb, b_Q); SYM(Kb, b_K); SYM(Vb, b_V);
    SYM(at_h, b_at_h); SYM(at_l, b_at_l);
    SYM(yq_h, b_yq_h); SYM(yq_l, b_yq_l);
    SYM(ff_h, b_ff_h); SYM(ff_l, b_ff_l);
    SYM(wf1_h, b_wf1_h); SYM(wf1_l, b_wf1_l);
    SYM(wf2_h, b_wf2_h); SYM(wf2_l, b_wf2_l);
    SYM(wf3_h, b_wf3_h); SYM(wf3_l, b_wf3_l);
    SYM(wqkv_h, b_wqkv_h); SYM(wqkv_l, b_wqkv_l);
    SYM(wo_h, b_wo_h); SYM(wo_l, b_wo_l);
    SYM(w1_h, b_w1_h); SYM(w1_l, b_w1_l);
    SYM(w2_h, b_w2_h); SYM(w2_l, b_w2_l);

    static cudaStream_t sA = nullptr, sB = nullptr;
    static cudaEvent_t ev0, ev1, ev2;
    if (!sA) {
        cudaStreamCreateWithFlags(&sA, cudaStreamNonBlocking);
        cudaStreamCreateWithFlags(&sB, cudaStreamNonBlocking);
        cudaEventCreateWithFlags(&ev0, cudaEventDisableTiming);
        cudaEventCreateWithFlags(&ev1, cudaEventDisableTiming);
        cudaEventCreateWithFlags(&ev2, cudaEventDisableTiming);
    }

    WS ws;
    ws.s[0] = Wf1;  ws.h[0] = wf1_h;  ws.l[0] = wf1_l;
    ws.s[1] = Wf2;  ws.h[1] = wf2_h;  ws.l[1] = wf2_l;
    ws.s[2] = Wf3;  ws.h[2] = wf3_h;  ws.l[2] = wf3_l;
    ws.s[3] = Wqkv; ws.h[3] = wqkv_h; ws.l[3] = wqkv_l;
    ws.s[4] = Wo;   ws.h[4] = wo_h;   ws.l[4] = wo_l;
    ws.s[5] = W1;   ws.h[5] = w1_h;   ws.l[5] = w1_l;
    ws.s[6] = W2;   ws.h[6] = w2_h;   ws.l[6] = w2_l;
    ws.off[0] = 0;       ws.off[1] = 131072;  ws.off[2] = 196608; ws.off[3] = 262144;
    ws.off[4] = 458752;  ws.off[5] = 524288;  ws.off[6] = 786432; ws.off[7] = 1048576;

    // fork point
    cudaEventRecord(ev0, 0);

    // branch A: weight splits
    cudaStreamWaitEvent(sA, ev0, 0);
    wsplit_k<<<4096, 256, 0, sA>>>(ws);
    cudaEventRecord(ev1, sA);

    // branch B: kv build + K/V projection (single-pass bf16)
    cudaStreamWaitEvent(sB, ev0, 0);
    build_kv_k<<<(LK * CM) / 256, 256, 0, sB>>>(x_ego, x_agent);
    cudaStreamWaitEvent(sB, ev1, 0);
    gemm_bs_k<OUT_KV, false, false, false, false><<<dim3(2 * CM / 64, LK / 64), 256, 0, sB>>>(
        kv_h, kv_l, wqkv_h + CM * CM, wqkv_l + CM * CM, bqkv + CM, nullptr,
        nullptr, Kb, Vb, LK, 2 * CM, CM);
    cudaEventRecord(ev2, sB);

    // main branch: matching, builds, compacted fusion MLP (q scattered from f3), Q proj
    match_all_k<<<1, 1024>>>(pos_ego, pos_agent);
    build_fi_qt_k<<<(FI_N + QT_N) / 256, 256>>>(x_ego, x_agent);
    cudaStreamWaitEvent(0, ev1, 0);
    gemm_bs_k<OUT_SPLIT, true, false, true, true><<<dim3(CM / 64, LE / 64), 256>>>(
        fi_h, fi_l, wf1_h, wf1_l, bf1, nullptr, nullptr, h1_h, h1_l, LE, CM, 2 * CM);
    gemm_bs_k<OUT_SPLIT, true, false, true, true><<<dim3(CM / 64, LE / 64), 256>>>(
        h1_h, h1_l, wf2_h, wf2_l, bf2, nullptr, nullptr, h2_h, h2_l, LE, CM, CM);
    gemm_bs_k<OUT_QSCAT, false, false, true, true><<<dim3(CM / 64, LE / 64), 256>>>(
        h2_h, h2_l, wf3_h, wf3_l, bf3, nullptr, p_q, q_h, q_l, LE, CM, CM);
    gemm_bs_k<OUT_BF16, false, false, false, false><<<dim3(CM / 64, LQ / 64), 256>>>(
        q_h, q_l, wqkv_h, wqkv_l, bqkv, nullptr, nullptr, Qb, nullptr, LQ, CM, CM);

    // join: attention needs K/V
    cudaStreamWaitEvent(0, ev2, 0);
    attn_mma_k<<<dim3(LQ / 64, HN), 128>>>(Qb, Kb, Vb, at_h, at_l);

    gemm_bs_k<OUT_F32, false, true, true, false><<<dim3(CM / 64, LQ / 64), 256>>>(
        at_h, at_l, wo_h, wo_l, bo, p_q, p_res1, nullptr, nullptr, LQ, CM, CM);
    ln_k<true><<<LQ, 256>>>(p_res1, g1, be1, p_yq, yq_h, yq_l);
    gemm_bs_k<OUT_SPLIT, true, false, true, false><<<dim3(DF / 64, LQ / 64), 256>>>(
        yq_h, yq_l, w1_h, w1_l, b1, nullptr, nullptr, ff_h, ff_l, LQ, DF, CM);
    gemm_bs_k<OUT_F32, false, true, true, false><<<dim3(CM / 64, LQ / 64), 256>>>(
        ff_h, ff_l, w2_h, w2_l, b2, p_yq, p_res2, nullptr, nullptr, LQ, CM, DF);
    ln_k<false><<<LQ, 256>>>(p_res2, g2, be2, out, nullptr, nullptr);
}